// round 9
// baseline (speedup 1.0000x reference)
#include <cuda_runtime.h>
#include <math.h>

#define BB 2
#define NN 512
#define CD 64
#define PF 128
#define DD 256
#define KNN 16
#define HH 8
#define DH 32
#define QKVD 768
#define CIN 195
#define KQ1P 52     // padded ceil(195/4) -> 52 kq = 208 k
#define KQD 64      // 256/4
#define NSPLIT 4

typedef unsigned long long ull;

// ---------------- scratch (device globals) ----------------
// pair-packed weights: [kh2 * NCP + cp] ulonglong2, .x=(w[2cp][2kh2],w[2cp+1][2kh2]), .y=same k+1
__device__ ulonglong2 g_W1v[104*128];
__device__ ulonglong2 g_Wr1v[128*128];
__device__ ulonglong2 g_Wr2v[128*128];
__device__ ulonglong2 g_Wov[128*128];
__device__ ulonglong2 g_Winv[128*384];
__device__ float4 g_Wgp[KQD*DD];
__device__ float g_mu[5];
__device__ float g_G[25];
__device__ __align__(16) float g_local[BB*NN*DD];
__device__ __align__(16) float g_regin[BB*NN*DD];
__device__ __align__(16) float g_qkv[BB*NN*QKVD];
__device__ float g_part[128*DD];
__device__ float g_gfeat[BB*DD];
__device__ float g_pm[BB*NSPLIT*HH*NN];
__device__ float g_pl[BB*NSPLIT*HH*NN];
__device__ __align__(16) float g_po[BB*NSPLIT*HH*NN*DH];

// ---------------- f32x2 packed math ----------------
__device__ __forceinline__ ull f2fma(ull a, ull b, ull c){ ull d; asm("fma.rn.f32x2 %0, %1, %2, %3;" : "=l"(d) : "l"(a), "l"(b), "l"(c)); return d; }
__device__ __forceinline__ ull f2mul(ull a, ull b){ ull d; asm("mul.rn.f32x2 %0, %1, %2;" : "=l"(d) : "l"(a), "l"(b)); return d; }
__device__ __forceinline__ ull pk2(float lo, float hi){ ull r; asm("mov.b64 %0, {%1,%2};" : "=l"(r) : "f"(lo), "f"(hi)); return r; }
__device__ __forceinline__ float2 up2(ull v){ float2 r; asm("mov.b64 {%0,%1}, %2;" : "=f"(r.x), "=f"(r.y) : "l"(v)); return r; }
__device__ __forceinline__ float rcp_fast(float x){ float r; asm("rcp.approx.ftz.f32 %0, %1;" : "=f"(r) : "f"(x)); return r; }
__device__ __forceinline__ float ex2_fast(float x){ float r; asm("ex2.approx.ftz.f32 %0, %1;" : "=f"(r) : "f"(x)); return r; }

__device__ __forceinline__ float gelu_fast(float x) {
    float xs = x * 0.70710678118654752440f;
    float ax = fabsf(xs);
    float t  = rcp_fast(fmaf(0.3275911f, ax, 1.0f));
    float p  = t * fmaf(t, fmaf(t, fmaf(t, fmaf(t, 1.061405429f, -1.453152027f),
                       1.421413741f), -0.284496736f), 0.254829592f);
    float e  = ex2_fast(-xs * xs * 1.4426950408889634f);
    float erfv = fmaf(-p, e, 1.0f);
    erfv = copysignf(erfv, xs);
    return 0.5f * x * (1.0f + erfv);
}

// ---------------- pipelined pair-GEMM core ----------------
// wp: weight base (+cp applied), stride WS ulonglong2 per kh2.
// ia/ib: two rows of duplicated inputs (ulonglong2 view).
// acc0/acc1 lanes = channels (2cp, 2cp+1), rows a/b.
template<int NKQ, int WS>
__device__ __forceinline__ void gemm_pair(const ulonglong2* __restrict__ wp,
                                          const ulonglong2* __restrict__ ia,
                                          const ulonglong2* __restrict__ ib,
                                          ull& acc0, ull& acc1) {
    ulonglong2 wbuf[8];
    #pragma unroll
    for (int t = 0; t < 8; t++) wbuf[t] = wp[t*WS];
    #pragma unroll
    for (int base = 0; base < NKQ; base += 4) {
        ulonglong2 wnext[8];
        if (base + 4 < NKQ) {
            #pragma unroll
            for (int t = 0; t < 8; t++) wnext[t] = wp[(2*(base+4) + t)*WS];
        }
        #pragma unroll
        for (int q = 0; q < 4; q++) {
            int kq = base + q;
            ulonglong2 a0 = ia[2*kq], a1 = ia[2*kq+1];
            ulonglong2 b0 = ib[2*kq], b1 = ib[2*kq+1];
            acc0 = f2fma(wbuf[2*q].x, a0.x, acc0);
            acc0 = f2fma(wbuf[2*q].y, a0.y, acc0);
            acc0 = f2fma(wbuf[2*q+1].x, a1.x, acc0);
            acc0 = f2fma(wbuf[2*q+1].y, a1.y, acc0);
            acc1 = f2fma(wbuf[2*q].x, b0.x, acc1);
            acc1 = f2fma(wbuf[2*q].y, b0.y, acc1);
            acc1 = f2fma(wbuf[2*q+1].x, b1.x, acc1);
            acc1 = f2fma(wbuf[2*q+1].y, b1.y, acc1);
        }
        if (base + 4 < NKQ) {
            #pragma unroll
            for (int t = 0; t < 8; t++) wbuf[t] = wnext[t];
        }
    }
}

// ---------------- K0: weight packing + 5x5 Gram ----------------
__device__ __forceinline__ float blockSumAll(float v, float* red) {
    #pragma unroll
    for (int o = 16; o > 0; o >>= 1) v += __shfl_down_sync(0xffffffffu, v, o);
    int w = threadIdx.x >> 5, l = threadIdx.x & 31;
    __syncthreads();
    if (l == 0) red[w] = v;
    __syncthreads();
    return red[0]+red[1]+red[2]+red[3]+red[4]+red[5]+red[6]+red[7];
}

#define NPREP 64
__global__ void prep_gram_kernel(const float* __restrict__ W1, const float* __restrict__ Wr1,
                                 const float* __restrict__ Wr2, const float* __restrict__ Win,
                                 const float* __restrict__ Wo, const float* __restrict__ Wg,
                                 const float* __restrict__ Ws, const float* __restrict__ bs) {
    if (blockIdx.x < NPREP) {
        int i = blockIdx.x * 256 + threadIdx.x;
        int stride = NPREP * 256;
        // W1 pair-pack (padded k)
        for (int e = i; e < 104*128; e += stride) {
            int kh2 = e >> 7, cp = e & 127;
            int k = 2*kh2;
            int c0 = 2*cp, c1 = 2*cp + 1;
            float w00 = (k   < CIN) ? W1[c0*CIN + k]   : 0.f;
            float w10 = (k   < CIN) ? W1[c1*CIN + k]   : 0.f;
            float w01 = (k+1 < CIN) ? W1[c0*CIN + k+1] : 0.f;
            float w11 = (k+1 < CIN) ? W1[c1*CIN + k+1] : 0.f;
            ulonglong2 v; v.x = pk2(w00, w10); v.y = pk2(w01, w11);
            g_W1v[e] = v;
        }
        // DD x DD matrices pair-pack
        for (int e = i; e < 128*128; e += stride) {
            int kh2 = e >> 7, cp = e & 127;
            int k = 2*kh2;
            int c0 = 2*cp, c1 = 2*cp + 1;
            ulonglong2 v;
            v.x = pk2(Wr1[c0*DD + k],   Wr1[c1*DD + k]);
            v.y = pk2(Wr1[c0*DD + k+1], Wr1[c1*DD + k+1]);
            g_Wr1v[e] = v;
            v.x = pk2(Wr2[c0*DD + k],   Wr2[c1*DD + k]);
            v.y = pk2(Wr2[c0*DD + k+1], Wr2[c1*DD + k+1]);
            g_Wr2v[e] = v;
            v.x = pk2(Wo[c0*DD + k],    Wo[c1*DD + k]);
            v.y = pk2(Wo[c0*DD + k+1],  Wo[c1*DD + k+1]);
            g_Wov[e] = v;
        }
        // Win pair-pack: cp global 0..383
        for (int e = i; e < 128*384; e += stride) {
            int kh2 = e / 384, cp = e % 384;
            int k = 2*kh2;
            int c0 = 2*cp, c1 = 2*cp + 1;
            ulonglong2 v;
            v.x = pk2(Win[c0*DD + k],   Win[c1*DD + k]);
            v.y = pk2(Win[c0*DD + k+1], Win[c1*DD + k+1]);
            g_Winv[e] = v;
        }
        // Wg float4 pack (gfeat path)
        for (int e = i; e < DD*KQD; e += stride) {
            int d = e >> 6, kq = e & 63;
            g_Wgp[kq*DD + d] = ((const float4*)(Wg + d*DD))[kq];
        }
    } else {
        __shared__ float red[8];
        int d = threadIdx.x;
        float4 w4 = *(const float4*)(Ws + d*4);
        float v[5] = {w4.x, w4.y, w4.z, w4.w, bs[d]};
        float mu[5];
        #pragma unroll
        for (int p = 0; p < 5; p++) mu[p] = blockSumAll(v[p], red) * (1.0f/DD);
        #pragma unroll
        for (int p = 0; p < 5; p++) v[p] -= mu[p];
        for (int p = 0; p < 5; p++)
            for (int q = 0; q < 5; q++) {
                float s = blockSumAll(v[p]*v[q], red) * (1.0f/DD);
                if (d == 0) g_G[p*5 + q] = s;
            }
        if (d == 0) { for (int p = 0; p < 5; p++) g_mu[p] = mu[p]; }
    }
}

// ---------------- LN stats for 8 rows (512-thread blocks) ----------------
__device__ __forceinline__ void ln_rows8_512(float (*h_sh)[DD], float (*stat)[2]) {
    int w = threadIdx.x >> 5, l = threadIdx.x & 31;
    if (w < 8) {
        float s = 0.f, s2 = 0.f;
        #pragma unroll
        for (int i = l; i < DD; i += 32) { float v = h_sh[w][i]; s += v; s2 += v*v; }
        #pragma unroll
        for (int o = 16; o > 0; o >>= 1) {
            s  += __shfl_down_sync(0xffffffffu, s,  o);
            s2 += __shfl_down_sync(0xffffffffu, s2, o);
        }
        if (l == 0) {
            float m = s * (1.0f/DD);
            stat[w][0] = m;
            stat[w][1] = rsqrtf(s2 * (1.0f/DD) - m*m + 1e-5f);
        }
    }
    __syncthreads();
}

// ---------------- K1: local encoder ----------------
__global__ void __launch_bounds__(512) local_encoder_kernel(
        const float* __restrict__ x, const float* __restrict__ pf,
        const float* __restrict__ xyz, const float* __restrict__ b1,
        const float* __restrict__ g1, const float* __restrict__ be1) {
    __shared__ __align__(16) ull in_dup[8][208];
    __shared__ float h_sh[8][DD];
    __shared__ float stat[8][2];
    __shared__ float part_sh[4][DD];
    int row0 = blockIdx.x * 8;
    int tid = threadIdx.x;
    int cp = tid & 127, rg = tid >> 7;   // rows 2rg, 2rg+1
    for (int idx = tid; idx < 8*208; idx += 512) {
        int r = idx / 208, k = idx % 208, row = row0 + r;
        float v;
        if (k < CD)          v = x[row*CD + k];
        else if (k < CD+PF)  v = pf[row*PF + (k - CD)];
        else if (k < CIN)    v = xyz[row*3 + (k - CD - PF)];
        else                 v = 0.f;
        in_dup[r][k] = pk2(v, v);
    }
    __syncthreads();
    ull acc0, acc1;
    { float2 bb = ((const float2*)b1)[cp]; acc0 = pk2(bb.x, bb.y); acc1 = acc0; }
    gemm_pair<KQ1P, 128>(g_W1v + cp,
                         (const ulonglong2*)in_dup[2*rg],
                         (const ulonglong2*)in_dup[2*rg+1], acc0, acc1);
    {
        float2 a = up2(acc0), b = up2(acc1);
        ((float2*)h_sh[2*rg])[cp]   = a;
        ((float2*)h_sh[2*rg+1])[cp] = b;
    }
    __syncthreads();
    ln_rows8_512(h_sh, stat);
    float2 gv = ((const float2*)g1)[cp];
    float2 bev = ((const float2*)be1)[cp];
    float p0 = 0.f, p1 = 0.f;
    #pragma unroll
    for (int rr = 0; rr < 2; rr++) {
        int r = 2*rg + rr;
        float m = stat[r][0], is = stat[r][1];
        float t0 = (h_sh[r][2*cp]   - m) * is * gv.x + bev.x;
        float t1 = (h_sh[r][2*cp+1] - m) * is * gv.y + bev.y;
        float e0 = gelu_fast(t0), e1 = gelu_fast(t1);
        p0 += e0; p1 += e1;
        float2 st; st.x = e0; st.y = e1;
        ((float2*)(g_local + (row0 + r)*DD))[cp] = st;
    }
    part_sh[rg][2*cp] = p0;
    part_sh[rg][2*cp+1] = p1;
    __syncthreads();
    if (tid < 256)
        g_part[blockIdx.x*DD + tid] = part_sh[0][tid] + part_sh[1][tid] + part_sh[2][tid] + part_sh[3][tid];
}

// ---------------- K2: fused gfeat(2 blocks) + kNN + gather + spatial ----------------
__global__ void knn_spatial_kernel(const float* __restrict__ xyz, const float* __restrict__ Ws,
                                   const float* __restrict__ bs, const float* __restrict__ gs,
                                   const float* __restrict__ bes,
                                   const float* __restrict__ bg, const float* __restrict__ gg,
                                   const float* __restrict__ beg,
                                   float* __restrict__ out) {
    __shared__ __align__(16) float xs[NN*3];
    __shared__ float  d2s[NN];
    __shared__ __align__(16) float sPXY[NN*2];
    __shared__ __align__(16) float sPZR[NN*2];
    __shared__ __align__(16) float sIM[NN*2];
    __shared__ float  wV[8*KNN];
    __shared__ int    wI[8*KNN];
    __shared__ int    sel[KNN];
    __shared__ float  sums6[6];
    __shared__ float  red6[8][6];
    int tid = threadIdx.x;
    int lane = tid & 31, warp = tid >> 5;

    if (blockIdx.x < BB) {
        float* lm = xs;
        float* red = d2s;
        int b = blockIdx.x;
        float s = 0.f;
        #pragma unroll 16
        for (int blk = 0; blk < 64; blk++) s += g_part[(b*64 + blk)*DD + tid];
        lm[tid] = s * (1.0f/NN);
        __syncthreads();
        float acc = bg[tid];
        for (int kq = 0; kq < KQD; kq++) {
            float4 l4 = ((const float4*)lm)[kq];
            float4 w = g_Wgp[kq*DD + tid];
            acc = fmaf(l4.x, w.x, acc);
            acc = fmaf(l4.y, w.y, acc);
            acc = fmaf(l4.z, w.z, acc);
            acc = fmaf(l4.w, w.w, acc);
        }
        float sv = acc, s2 = acc*acc;
        #pragma unroll
        for (int o = 16; o > 0; o >>= 1) {
            sv += __shfl_down_sync(0xffffffffu, sv, o);
            s2 += __shfl_down_sync(0xffffffffu, s2, o);
        }
        if (lane == 0) { red[warp] = sv; red[8 + warp] = s2; }
        __syncthreads();
        float S = 0.f, S2 = 0.f;
        #pragma unroll
        for (int t = 0; t < 8; t++) { S += red[t]; S2 += red[8 + t]; }
        float m = S * (1.0f/DD);
        float is = rsqrtf(S2 * (1.0f/DD) - m*m + 1e-5f);
        g_gfeat[b*DD + tid] = (acc - m) * is * gg[tid] + beg[tid];
        return;
    }

    int bid = blockIdx.x - BB;
    int b = bid >> 9, i = bid & 511;
    for (int idx = tid; idx < NN*3; idx += 256) xs[idx] = xyz[b*NN*3 + idx];
    __syncthreads();
    float xi = xs[i*3], yi = xs[i*3+1], zi = xs[i*3+2];
    float lsx = 0.f, lsy = 0.f, lsz = 0.f, lsr = 0.f, lsi = 0.f, lsm = 0.f;
    #pragma unroll
    for (int jj = 0; jj < 2; jj++) {
        int j = tid + jj*256;
        float a = xi - xs[j*3], bc = yi - xs[j*3+1], c = zi - xs[j*3+2];
        float d2 = a*a + bc*bc + c*c;
        float rd = sqrtf(d2);
        d2s[j] = d2;
        float cf[5] = {a, bc, c, rd, 1.0f};
        float mm = fmaf(a, g_mu[0], fmaf(bc, g_mu[1], fmaf(c, g_mu[2], fmaf(rd, g_mu[3], g_mu[4]))));
        float var = 0.f;
        #pragma unroll
        for (int p = 0; p < 5; p++) {
            float t = 0.f;
            #pragma unroll
            for (int q = 0; q < 5; q++) t = fmaf(g_G[p*5 + q], cf[q], t);
            var = fmaf(cf[p], t, var);
        }
        float is = rsqrtf(var + 1e-5f);
        float px = is*a, py = is*bc, pz = is*c, pr = is*rd, pm = mm*is;
        int base = (j >> 1)*4 + (j & 1);
        sPXY[base]     = px;  sPXY[base + 2] = py;
        sPZR[base]     = pz;  sPZR[base + 2] = pr;
        sIM[base]      = is;  sIM[base + 2]  = pm;
        lsx += px; lsy += py; lsz += pz; lsr += pr; lsi += is; lsm += pm;
    }
    #pragma unroll
    for (int o = 16; o > 0; o >>= 1) {
        lsx += __shfl_down_sync(0xffffffffu, lsx, o);
        lsy += __shfl_down_sync(0xffffffffu, lsy, o);
        lsz += __shfl_down_sync(0xffffffffu, lsz, o);
        lsr += __shfl_down_sync(0xffffffffu, lsr, o);
        lsi += __shfl_down_sync(0xffffffffu, lsi, o);
        lsm += __shfl_down_sync(0xffffffffu, lsm, o);
    }
    if (lane == 0) {
        red6[warp][0] = lsx; red6[warp][1] = lsy; red6[warp][2] = lsz;
        red6[warp][3] = lsr; red6[warp][4] = lsi; red6[warp][5] = lsm;
    }
    __syncthreads();
    if (tid < 6) {
        float t = 0.f;
        #pragma unroll
        for (int w = 0; w < 8; w++) t += red6[w][tid];
        sums6[tid] = t;
    }
    {
        int j0 = warp*64 + lane, j1 = j0 + 32;
        float v0 = d2s[j0], v1 = d2s[j1];
        #pragma unroll
        for (int it = 0; it < KNN; it++) {
            float cv; int ci;
            if (v1 < v0) { cv = v1; ci = j1; } else { cv = v0; ci = j0; }
            #pragma unroll
            for (int o = 16; o > 0; o >>= 1) {
                float ov = __shfl_xor_sync(0xffffffffu, cv, o);
                int   oi = __shfl_xor_sync(0xffffffffu, ci, o);
                if (ov < cv || (ov == cv && oi < ci)) { cv = ov; ci = oi; }
            }
            if (lane == 0) { wV[warp*KNN + it] = cv; wI[warp*KNN + it] = ci; }
            if (ci == j0) v0 = 3.4e38f;
            if (ci == j1) v1 = 3.4e38f;
        }
    }
    __syncthreads();
    if (warp == 0) {
        float mv[4]; int mi[4];
        #pragma unroll
        for (int q = 0; q < 4; q++) { mv[q] = wV[q*32 + lane]; mi[q] = wI[q*32 + lane]; }
        #pragma unroll
        for (int it = 0; it < KNN; it++) {
            float cv = mv[0]; int ci = mi[0];
            #pragma unroll
            for (int q = 1; q < 4; q++)
                if (mv[q] < cv || (mv[q] == cv && mi[q] < ci)) { cv = mv[q]; ci = mi[q]; }
            #pragma unroll
            for (int o = 16; o > 0; o >>= 1) {
                float ov = __shfl_xor_sync(0xffffffffu, cv, o);
                int   oi = __shfl_xor_sync(0xffffffffu, ci, o);
                if (ov < cv || (ov == cv && oi < ci)) { cv = ov; ci = oi; }
            }
            if (lane == 0) sel[it] = ci;
            #pragma unroll
            for (int q = 0; q < 4; q++) if (mi[q] == ci) mv[q] = 3.4e38f;
        }
    }
    __syncthreads();
    float sg = 0.f;
    #pragma unroll
    for (int k = 0; k < KNN; k++) sg += g_local[(b*NN + sel[k])*DD + tid];
    g_regin[(b*NN + i)*DD + tid] = sg * (1.0f/KNN);
    float4 wv4 = *(const float4*)(Ws + tid*4);
    float gd = gs[tid], bed = bes[tid];
    float wxp = gd*wv4.x, wyp = gd*wv4.y, wzp = gd*wv4.z, wwp = gd*wv4.w;
    float bsp = gd*bs[tid];
    float sumT = wxp*sums6[0] + wyp*sums6[1] + wzp*sums6[2] + wwp*sums6[3]
               + bsp*sums6[4] - gd*sums6[5] + bed*(float)NN;
    const ull WX = pk2(wxp, wxp), WY = pk2(wyp, wyp);
    const ull WZ = pk2(wzp, wzp), WW = pk2(wwp, wwp);
    const ull BSP = pk2(bsp, bsp), NGD = pk2(-gd, -gd), BED = pk2(bed, bed);
    const ull ONE2  = pk2(1.0f, 1.0f);
    const ull ISQ2  = pk2(0.70710678118654752440f, 0.70710678118654752440f);
    const ull CP    = pk2(0.47047f, 0.47047f);
    const ull C3    = pk2(-0.7478556f, -0.7478556f);
    const ull C2    = pk2(0.0958798f, 0.0958798f);
    const ull C1    = pk2(-0.3480242f, -0.3480242f);
    const ull NL2E  = pk2(-1.4426950408889634f, -1.4426950408889634f);
    const ull ABSM  = 0x7FFFFFFF7FFFFFFFull;
    const ull SGNM  = 0x8000000080000000ull;
    const ulonglong2* pXY = (const ulonglong2*)sPXY;
    const ulonglong2* pZR = (const ulonglong2*)sPZR;
    const ulonglong2* pIM = (const ulonglong2*)sIM;
    ull acc2 = 0ull;
    #pragma unroll 2
    for (int j2 = 0; j2 < NN/2; j2++) {
        ulonglong2 axy = pXY[j2];
        ulonglong2 azr = pZR[j2];
        ulonglong2 aim = pIM[j2];
        ull t = f2fma(NGD, aim.y, BED);
        t = f2fma(BSP, aim.x, t);
        t = f2fma(WW, azr.y, t);
        t = f2fma(WZ, azr.x, t);
        t = f2fma(WY, axy.y, t);
        t = f2fma(WX, axy.x, t);
        ull xsp = f2mul(t, ISQ2);
        ull axp = xsp & ABSM;
        ull den = f2fma(axp, CP, ONE2);
        float2 dv = up2(den);
        ull tt = pk2(rcp_fast(dv.x), rcp_fast(dv.y));
        ull p = f2fma(C3, tt, C2);
        p = f2fma(p, tt, C1);
        p = f2mul(p, tt);
        ull m2 = f2mul(xsp, xsp);
        ull ea = f2mul(m2, NL2E);
        float2 ev = up2(ea);
        ull e2 = pk2(ex2_fast(ev.x), ex2_fast(ev.y));
        ull erf2 = f2fma(p, e2, ONE2);
        erf2 = erf2 | (xsp & SGNM);
        acc2 = f2fma(t, erf2, acc2);
    }
    float2 av = up2(acc2);
    out[(b*NN + i)*DD + tid] = 0.5f * (sumT + av.x + av.y) * (1.0f/NN);
}

// ---------------- K3: region MLP + combined + QKV (pipelined pair GEMMs) ----------------
__global__ void __launch_bounds__(512) region_qkv_kernel(
        const float* __restrict__ br1, const float* __restrict__ gr1,
        const float* __restrict__ ber1, const float* __restrict__ br2,
        const float* __restrict__ gr2, const float* __restrict__ ber2,
        const float* __restrict__ bin_) {
    __shared__ __align__(16) ull in_dup[8][DD];
    __shared__ float h_sh[8][DD];
    __shared__ float stat[8][2];
    int row0 = blockIdx.x * 8;
    int b = row0 >> 9;
    int tid = threadIdx.x;
    int cp = tid & 127, rg = tid >> 7;
    for (int idx = tid; idx < 8*DD; idx += 512) {
        int r = idx >> 8, k = idx & 255;
        float v = g_regin[(row0 + r)*DD + k];
        in_dup[r][k] = pk2(v, v);
    }
    __syncthreads();
    const ulonglong2* ia = (const ulonglong2*)in_dup[2*rg];
    const ulonglong2* ib = (const ulonglong2*)in_dup[2*rg+1];
    ull acc0, acc1;
    { float2 bb = ((const float2*)br1)[cp]; acc0 = pk2(bb.x, bb.y); acc1 = acc0; }
    gemm_pair<KQD, 128>(g_Wr1v + cp, ia, ib, acc0, acc1);
    {
        float2 a = up2(acc0), bq = up2(acc1);
        ((float2*)h_sh[2*rg])[cp]   = a;
        ((float2*)h_sh[2*rg+1])[cp] = bq;
    }
    __syncthreads();
    ln_rows8_512(h_sh, stat);
    {
        float2 g1v = ((const float2*)gr1)[cp];
        float2 b1v = ((const float2*)ber1)[cp];
        #pragma unroll
        for (int rr = 0; rr < 2; rr++) {
            int r = 2*rg + rr;
            float m = stat[r][0], is = stat[r][1];
            float t0 = (h_sh[r][2*cp]   - m) * is * g1v.x + b1v.x;
            float t1 = (h_sh[r][2*cp+1] - m) * is * g1v.y + b1v.y;
            float e0 = gelu_fast(t0), e1 = gelu_fast(t1);
            in_dup[r][2*cp]   = pk2(e0, e0);
            in_dup[r][2*cp+1] = pk2(e1, e1);
        }
    }
    __syncthreads();
    { float2 bb = ((const float2*)br2)[cp]; acc0 = pk2(bb.x, bb.y); acc1 = acc0; }
    gemm_pair<KQD, 128>(g_Wr2v + cp, ia, ib, acc0, acc1);
    __syncthreads();   // all in_dup reads done before combined overwrite
    {
        float2 a = up2(acc0), bq = up2(acc1);
        ((float2*)h_sh[2*rg])[cp]   = a;
        ((float2*)h_sh[2*rg+1])[cp] = bq;
    }
    __syncthreads();
    ln_rows8_512(h_sh, stat);
    {
        float2 g2v = ((const float2*)gr2)[cp];
        float2 b2v = ((const float2*)ber2)[cp];
        float2 gf = ((const float2*)(g_gfeat + b*DD))[cp];
        #pragma unroll
        for (int rr = 0; rr < 2; rr++) {
            int r = 2*rg + rr;
            float m = stat[r][0], is = stat[r][1];
            float t0 = (h_sh[r][2*cp]   - m) * is * g2v.x + b2v.x;
            float t1 = (h_sh[r][2*cp+1] - m) * is * g2v.y + b2v.y;
            float2 lo = ((const float2*)(g_local + (row0 + r)*DD))[cp];
            float c0 = lo.x + t0 + gf.x;
            float c1 = lo.y + t1 + gf.y;
            in_dup[r][2*cp]   = pk2(c0, c0);
            in_dup[r][2*cp+1] = pk2(c1, c1);
        }
    }
    __syncthreads();
    // ---- QKV: 3 pipelined passes ----
    #pragma unroll
    for (int co = 0; co < 3; co++) {
        ull qa0, qa1;
        { float2 bb = ((const float2*)bin_)[co*128 + cp]; qa0 = pk2(bb.x, bb.y); qa1 = qa0; }
        gemm_pair<KQD, 384>(g_Winv + co*128 + cp, ia, ib, qa0, qa1);
        float2 a = up2(qa0), bq = up2(qa1);
        ((float2*)(g_qkv + (row0 + 2*rg)*QKVD + co*256))[cp]   = a;
        ((float2*)(g_qkv + (row0 + 2*rg+1)*QKVD + co*256))[cp] = bq;
    }
}

// ---------------- K4: attention split-KV, f32x2-packed ----------------
__global__ void attn_kernel() {
    __shared__ __align__(16) float Ksh[128][DH];
    __shared__ __align__(16) float Vsh[128][DH];
    int z = blockIdx.z;
    int b = z >> 2, s = z & 3;
    int h = blockIdx.y;
    int qi = blockIdx.x * 64 + threadIdx.x;
    int tid = threadIdx.x;
    const float scale = 0.17677669529663688f * 1.4426950408889634f;
    ull qp[16];
    const float* qrow = g_qkv + (b*NN + qi)*QKVD + h*DH;
    #pragma unroll
    for (int d4 = 0; d4 < 8; d4++) {
        float4 v = *(const float4*)(qrow + d4*4);
        qp[d4*2]   = pk2(v.x*scale, v.y*scale);
        qp[d4*2+1] = pk2(v.z*scale, v.w*scale);
    }
    int jt = s * 128;
    for (int idx = tid; idx < 128*DH; idx += 64) {
        int jj = idx >> 5, dd = idx & 31;
        int base = (b*NN + jt + jj)*QKVD + h*DH + dd;
        Ksh[jj][dd] = g_qkv[base + DD];
        Vsh[jj][dd] = g_qkv[base + 2*DD];
    }
    __syncthreads();
    float m = -1e30f, l = 0.f;
    ull op[16];
    #pragma unroll
    for (int t = 0; t < 16; t++) op[t] = 0ull;
    for (int jj = 0; jj < 128; jj++) {
        const ulonglong2* kp = (const ulonglong2*)Ksh[jj];
        ull s2a = 0ull, s2b = 0ull;
        #pragma unroll
        for (int t = 0; t < 8; t++) {
            ulonglong2 kv = kp[t];
            s2a = f2fma(qp[t*2],   kv.x, s2a);
            s2b = f2fma(qp[t*2+1], kv.y, s2b);
        }
        float2 sva = up2(s2a), svb = up2(s2b);
        float sc = (sva.x + sva.y) + (svb.x + svb.y);
        if (sc > m) {
            float corr = ex2_fast(m - sc);
            l *= corr;
            ull c2 = pk2(corr, corr);
            #pragma unroll
            for (int t = 0; t < 16; t++) op[t] = f2mul(op[t], c2);
            m = sc;
        }
        float p = ex2_fast(sc - m);
        l += p;
        ull pp = pk2(p, p);
        const ulonglong2* vp = (const ulonglong2*)Vsh[jj];
        #pragma unroll
        for (int t = 0; t < 8; t++) {
            ulonglong2 vv = vp[t];
            op[t*2]   = f2fma(pp, vv.x, op[t*2]);
            op[t*2+1] = f2fma(pp, vv.y, op[t*2+1]);
        }
    }
    int pb = ((b*NSPLIT + s)*HH + h)*NN + qi;
    g_pm[pb] = m;
    g_pl[pb] = l;
    float* po = g_po + pb*DH;
    #pragma unroll
    for (int t = 0; t < 16; t++) {
        float2 ov = up2(op[t]);
        po[t*2]   = ov.x;
        po[t*2+1] = ov.y;
    }
}

// ---------------- K5: merge splits + out += o @ Wo.T + bo ----------------
__global__ void __launch_bounds__(512) oproj_kernel(const float* __restrict__ bo, float* __restrict__ out) {
    __shared__ float esc[8][HH][NSPLIT];
    __shared__ __align__(16) ull in_dup[8][DD];
    int row0 = blockIdx.x * 8;
    int b = row0 >> 9;
    int q0 = row0 & 511;
    int tid = threadIdx.x;
    int cp = tid & 127, rg = tid >> 7;
    if (tid < 64) {
        int r = tid >> 3, h = tid & 7;
        int q = q0 + r;
        float ms[NSPLIT];
        float mx = -1e30f;
        #pragma unroll
        for (int s = 0; s < NSPLIT; s++) {
            ms[s] = g_pm[((b*NSPLIT + s)*HH + h)*NN + q];
            mx = fmaxf(mx, ms[s]);
        }
        float lsum = 0.f;
        #pragma unroll
        for (int s = 0; s < NSPLIT; s++)
            lsum += g_pl[((b*NSPLIT + s)*HH + h)*NN + q] * ex2_fast(ms[s] - mx);
        float inv = 1.0f / lsum;
        #pragma unroll
        for (int s = 0; s < NSPLIT; s++)
            esc[r][h][s] = ex2_fast(ms[s] - mx) * inv;
    }
    __syncthreads();
    int ch0 = 2*cp;
    int h = ch0 >> 5, dh = ch0 & 31;
    #pragma unroll
    for (int rr = 0; rr < 2; rr++) {
        int r = 2*rg + rr;
        float o0 = 0.f, o1 = 0.f;
        #pragma unroll
        for (int s = 0; s < NSPLIT; s++) {
            const float2* base = (const float2*)(g_po + (((b*NSPLIT + s)*HH + h)*NN + q0 + r)*DH + dh);
            float2 pv = base[0];
            float e = esc[r][h][s];
            o0 = fmaf(pv.x, e, o0);
            o1 = fmaf(pv.y, e, o1);
        }
        in_dup[r][ch0]   = pk2(o0, o0);
        in_dup[r][ch0+1] = pk2(o1, o1);
    }
    __syncthreads();
    ull acc0, acc1;
    { float2 bb = ((const float2*)bo)[cp]; acc0 = pk2(bb.x, bb.y); acc1 = acc0; }
    gemm_pair<KQD, 128>(g_Wov + cp,
                        (const ulonglong2*)in_dup[2*rg],
                        (const ulonglong2*)in_dup[2*rg+1], acc0, acc1);
    {
        float2 a = up2(acc0), bq = up2(acc1);
        float2* o0p = (float2*)(out + (row0 + 2*rg)*DD) + cp;
        float2* o1p = (float2*)(out + (row0 + 2*rg+1)*DD) + cp;
        float2 v0 = *o0p, v1 = *o1p;
        v0.x += a.x;  v0.y += a.y;
        v1.x += bq.x; v1.y += bq.y;
        *o0p = v0; *o1p = v1;
    }
}

// ---------------- launch ----------------
extern "C" void kernel_launch(void* const* d_in, const int* in_sizes, int n_in,
                              void* d_out, int out_size) {
    const float* x    = (const float*)d_in[0];
    const float* pf   = (const float*)d_in[1];
    const float* xyz  = (const float*)d_in[2];
    const float* W1   = (const float*)d_in[3];
    const float* b1   = (const float*)d_in[4];
    const float* g1   = (const float*)d_in[5];
    const float* be1  = (const float*)d_in[6];
    const float* Wr1  = (const float*)d_in[7];
    const float* br1  = (const float*)d_in[8];
    const float* gr1  = (const float*)d_in[9];
    const float* ber1 = (const float*)d_in[10];
    const float* Wr2  = (const float*)d_in[11];
    const float* br2  = (const float*)d_in[12];
    const float* gr2  = (const float*)d_in[13];
    const float* ber2 = (const float*)d_in[14];
    const float* Wg   = (const float*)d_in[15];
    const float* bg   = (const float*)d_in[16];
    const float* gg   = (const float*)d_in[17];
    const float* beg  = (const float*)d_in[18];
    const float* Win  = (const float*)d_in[19];
    const float* bin_ = (const float*)d_in[20];
    const float* Wo   = (const float*)d_in[21];
    const float* bo   = (const float*)d_in[22];
    const float* Ws   = (const float*)d_in[23];
    const float* bs   = (const float*)d_in[24];
    const float* gs   = (const float*)d_in[25];
    const float* bes  = (const float*)d_in[26];
    float* out = (float*)d_out;

    prep_gram_kernel<<<NPREP + 1, 256>>>(W1, Wr1, Wr2, Win, Wo, Wg, Ws, bs);
    local_encoder_kernel<<<128, 512>>>(x, pf, xyz, b1, g1, be1);
    knn_spatial_kernel<<<BB*NN + BB, 256>>>(xyz, Ws, bs, gs, bes, bg, gg, beg, out);
    region_qkv_kernel<<<128, 512>>>(br1, gr1, ber1, br2, gr2, ber2, bin_);
    dim3 ag(NN/64, HH, BB*NSPLIT);
    attn_kernel<<<ag, 64>>>();
    oproj_kernel<<<128, 512>>>(bo, out);
}

// round 10
// speedup vs baseline: 1.3922x; 1.3922x over previous
#include <cuda_runtime.h>
#include <math.h>

#define BB 2
#define NN 512
#define CD 64
#define PF 128
#define DD 256
#define KNN 16
#define HH 8
#define DH 32
#define QKVD 768
#define CIN 195
#define KQ1P 52     // padded ceil(195/4) -> 52 kq = 208 k
#define KQD 64      // 256/4
#define NSPLIT 4

typedef unsigned long long ull;

// ---------------- scratch (device globals) ----------------
// pair-packed weights: [kh2 * NCP + cp] ulonglong2, .x=(w[2cp][2kh2],w[2cp+1][2kh2]), .y=same k+1
__device__ ulonglong2 g_W1v[104*128];
__device__ ulonglong2 g_Wr1v[128*128];
__device__ ulonglong2 g_Wr2v[128*128];
__device__ ulonglong2 g_Wov[128*128];
__device__ ulonglong2 g_Winv[128*384];
__device__ float4 g_Wgp[KQD*DD];
__device__ float g_mu[5];
__device__ float g_G[25];
__device__ __align__(16) float g_local[BB*NN*DD];
__device__ __align__(16) float g_regin[BB*NN*DD];
__device__ __align__(16) float g_qkv[BB*NN*QKVD];
__device__ float g_part[128*DD];
__device__ float g_gfeat[BB*DD];
__device__ float g_pm[BB*NSPLIT*HH*NN];
__device__ float g_pl[BB*NSPLIT*HH*NN];
__device__ __align__(16) float g_po[BB*NSPLIT*HH*NN*DH];

// ---------------- f32x2 packed math ----------------
__device__ __forceinline__ ull f2fma(ull a, ull b, ull c){ ull d; asm("fma.rn.f32x2 %0, %1, %2, %3;" : "=l"(d) : "l"(a), "l"(b), "l"(c)); return d; }
__device__ __forceinline__ ull f2mul(ull a, ull b){ ull d; asm("mul.rn.f32x2 %0, %1, %2;" : "=l"(d) : "l"(a), "l"(b)); return d; }
__device__ __forceinline__ ull pk2(float lo, float hi){ ull r; asm("mov.b64 %0, {%1,%2};" : "=l"(r) : "f"(lo), "f"(hi)); return r; }
__device__ __forceinline__ float2 up2(ull v){ float2 r; asm("mov.b64 {%0,%1}, %2;" : "=f"(r.x), "=f"(r.y) : "l"(v)); return r; }
__device__ __forceinline__ float rcp_fast(float x){ float r; asm("rcp.approx.ftz.f32 %0, %1;" : "=f"(r) : "f"(x)); return r; }
__device__ __forceinline__ float ex2_fast(float x){ float r; asm("ex2.approx.ftz.f32 %0, %1;" : "=f"(r) : "f"(x)); return r; }

__device__ __forceinline__ float gelu_fast(float x) {
    float xs = x * 0.70710678118654752440f;
    float ax = fabsf(xs);
    float t  = rcp_fast(fmaf(0.3275911f, ax, 1.0f));
    float p  = t * fmaf(t, fmaf(t, fmaf(t, fmaf(t, 1.061405429f, -1.453152027f),
                       1.421413741f), -0.284496736f), 0.254829592f);
    float e  = ex2_fast(-xs * xs * 1.4426950408889634f);
    float erfv = fmaf(-p, e, 1.0f);
    erfv = copysignf(erfv, xs);
    return 0.5f * x * (1.0f + erfv);
}

// ---------------- pipelined pair-GEMM core (depth-2 double buffer, spill-safe) ----------------
// wp: weight base (+cp applied), stride WS ulonglong2 per kh2.
// ia/ib: two rows of duplicated inputs (ulonglong2 view).
// acc0/acc1 lanes = channels (2cp, 2cp+1), rows a/b.
// NKQ must be even.
template<int NKQ, int WS>
__device__ __forceinline__ void gemm_pair(const ulonglong2* __restrict__ wp,
                                          const ulonglong2* __restrict__ ia,
                                          const ulonglong2* __restrict__ ib,
                                          ull& acc0, ull& acc1) {
    ulonglong2 w0 = wp[0], w1 = wp[WS], w2 = wp[2*WS], w3 = wp[3*WS];
    #pragma unroll
    for (int base = 0; base < NKQ; base += 2) {
        ulonglong2 n0, n1, n2, n3;
        if (base + 2 < NKQ) {
            n0 = wp[(2*base+4)*WS]; n1 = wp[(2*base+5)*WS];
            n2 = wp[(2*base+6)*WS]; n3 = wp[(2*base+7)*WS];
        }
        {   // kq = base
            ulonglong2 a0 = ia[2*base], a1 = ia[2*base+1];
            ulonglong2 b0 = ib[2*base], b1 = ib[2*base+1];
            acc0 = f2fma(w0.x, a0.x, acc0); acc0 = f2fma(w0.y, a0.y, acc0);
            acc0 = f2fma(w1.x, a1.x, acc0); acc0 = f2fma(w1.y, a1.y, acc0);
            acc1 = f2fma(w0.x, b0.x, acc1); acc1 = f2fma(w0.y, b0.y, acc1);
            acc1 = f2fma(w1.x, b1.x, acc1); acc1 = f2fma(w1.y, b1.y, acc1);
        }
        {   // kq = base+1
            ulonglong2 a0 = ia[2*base+2], a1 = ia[2*base+3];
            ulonglong2 b0 = ib[2*base+2], b1 = ib[2*base+3];
            acc0 = f2fma(w2.x, a0.x, acc0); acc0 = f2fma(w2.y, a0.y, acc0);
            acc0 = f2fma(w3.x, a1.x, acc0); acc0 = f2fma(w3.y, a1.y, acc0);
            acc1 = f2fma(w2.x, b0.x, acc1); acc1 = f2fma(w2.y, b0.y, acc1);
            acc1 = f2fma(w3.x, b1.x, acc1); acc1 = f2fma(w3.y, b1.y, acc1);
        }
        if (base + 2 < NKQ) { w0 = n0; w1 = n1; w2 = n2; w3 = n3; }
    }
}

// ---------------- K0: weight packing + 5x5 Gram ----------------
__device__ __forceinline__ float blockSumAll(float v, float* red) {
    #pragma unroll
    for (int o = 16; o > 0; o >>= 1) v += __shfl_down_sync(0xffffffffu, v, o);
    int w = threadIdx.x >> 5, l = threadIdx.x & 31;
    __syncthreads();
    if (l == 0) red[w] = v;
    __syncthreads();
    return red[0]+red[1]+red[2]+red[3]+red[4]+red[5]+red[6]+red[7];
}

#define NPREP 64
__global__ void prep_gram_kernel(const float* __restrict__ W1, const float* __restrict__ Wr1,
                                 const float* __restrict__ Wr2, const float* __restrict__ Win,
                                 const float* __restrict__ Wo, const float* __restrict__ Wg,
                                 const float* __restrict__ Ws, const float* __restrict__ bs) {
    if (blockIdx.x < NPREP) {
        int i = blockIdx.x * 256 + threadIdx.x;
        int stride = NPREP * 256;
        // W1 pair-pack (padded k)
        for (int e = i; e < 104*128; e += stride) {
            int kh2 = e >> 7, cp = e & 127;
            int k = 2*kh2;
            int c0 = 2*cp, c1 = 2*cp + 1;
            float w00 = (k   < CIN) ? W1[c0*CIN + k]   : 0.f;
            float w10 = (k   < CIN) ? W1[c1*CIN + k]   : 0.f;
            float w01 = (k+1 < CIN) ? W1[c0*CIN + k+1] : 0.f;
            float w11 = (k+1 < CIN) ? W1[c1*CIN + k+1] : 0.f;
            ulonglong2 v; v.x = pk2(w00, w10); v.y = pk2(w01, w11);
            g_W1v[e] = v;
        }
        // DD x DD matrices pair-pack
        for (int e = i; e < 128*128; e += stride) {
            int kh2 = e >> 7, cp = e & 127;
            int k = 2*kh2;
            int c0 = 2*cp, c1 = 2*cp + 1;
            ulonglong2 v;
            v.x = pk2(Wr1[c0*DD + k],   Wr1[c1*DD + k]);
            v.y = pk2(Wr1[c0*DD + k+1], Wr1[c1*DD + k+1]);
            g_Wr1v[e] = v;
            v.x = pk2(Wr2[c0*DD + k],   Wr2[c1*DD + k]);
            v.y = pk2(Wr2[c0*DD + k+1], Wr2[c1*DD + k+1]);
            g_Wr2v[e] = v;
            v.x = pk2(Wo[c0*DD + k],    Wo[c1*DD + k]);
            v.y = pk2(Wo[c0*DD + k+1],  Wo[c1*DD + k+1]);
            g_Wov[e] = v;
        }
        // Win pair-pack: cp global 0..383
        for (int e = i; e < 128*384; e += stride) {
            int kh2 = e / 384, cp = e % 384;
            int k = 2*kh2;
            int c0 = 2*cp, c1 = 2*cp + 1;
            ulonglong2 v;
            v.x = pk2(Win[c0*DD + k],   Win[c1*DD + k]);
            v.y = pk2(Win[c0*DD + k+1], Win[c1*DD + k+1]);
            g_Winv[e] = v;
        }
        // Wg float4 pack (gfeat path)
        for (int e = i; e < DD*KQD; e += stride) {
            int d = e >> 6, kq = e & 63;
            g_Wgp[kq*DD + d] = ((const float4*)(Wg + d*DD))[kq];
        }
    } else {
        __shared__ float red[8];
        int d = threadIdx.x;
        float4 w4 = *(const float4*)(Ws + d*4);
        float v[5] = {w4.x, w4.y, w4.z, w4.w, bs[d]};
        float mu[5];
        #pragma unroll
        for (int p = 0; p < 5; p++) mu[p] = blockSumAll(v[p], red) * (1.0f/DD);
        #pragma unroll
        for (int p = 0; p < 5; p++) v[p] -= mu[p];
        for (int p = 0; p < 5; p++)
            for (int q = 0; q < 5; q++) {
                float s = blockSumAll(v[p]*v[q], red) * (1.0f/DD);
                if (d == 0) g_G[p*5 + q] = s;
            }
        if (d == 0) { for (int p = 0; p < 5; p++) g_mu[p] = mu[p]; }
    }
}

// ---------------- LN stats for 8 rows (512-thread blocks) ----------------
__device__ __forceinline__ void ln_rows8_512(float (*h_sh)[DD], float (*stat)[2]) {
    int w = threadIdx.x >> 5, l = threadIdx.x & 31;
    if (w < 8) {
        float s = 0.f, s2 = 0.f;
        #pragma unroll
        for (int i = l; i < DD; i += 32) { float v = h_sh[w][i]; s += v; s2 += v*v; }
        #pragma unroll
        for (int o = 16; o > 0; o >>= 1) {
            s  += __shfl_down_sync(0xffffffffu, s,  o);
            s2 += __shfl_down_sync(0xffffffffu, s2, o);
        }
        if (l == 0) {
            float m = s * (1.0f/DD);
            stat[w][0] = m;
            stat[w][1] = rsqrtf(s2 * (1.0f/DD) - m*m + 1e-5f);
        }
    }
    __syncthreads();
}

// ---------------- K1: local encoder ----------------
__global__ void __launch_bounds__(512, 1) local_encoder_kernel(
        const float* __restrict__ x, const float* __restrict__ pf,
        const float* __restrict__ xyz, const float* __restrict__ b1,
        const float* __restrict__ g1, const float* __restrict__ be1) {
    __shared__ __align__(16) ull in_dup[8][208];
    __shared__ float h_sh[8][DD];
    __shared__ float stat[8][2];
    __shared__ float part_sh[4][DD];
    int row0 = blockIdx.x * 8;
    int tid = threadIdx.x;
    int cp = tid & 127, rg = tid >> 7;   // rows 2rg, 2rg+1
    for (int idx = tid; idx < 8*208; idx += 512) {
        int r = idx / 208, k = idx % 208, row = row0 + r;
        float v;
        if (k < CD)          v = x[row*CD + k];
        else if (k < CD+PF)  v = pf[row*PF + (k - CD)];
        else if (k < CIN)    v = xyz[row*3 + (k - CD - PF)];
        else                 v = 0.f;
        in_dup[r][k] = pk2(v, v);
    }
    __syncthreads();
    ull acc0, acc1;
    { float2 bb = ((const float2*)b1)[cp]; acc0 = pk2(bb.x, bb.y); acc1 = acc0; }
    gemm_pair<KQ1P, 128>(g_W1v + cp,
                         (const ulonglong2*)in_dup[2*rg],
                         (const ulonglong2*)in_dup[2*rg+1], acc0, acc1);
    {
        float2 a = up2(acc0), b = up2(acc1);
        ((float2*)h_sh[2*rg])[cp]   = a;
        ((float2*)h_sh[2*rg+1])[cp] = b;
    }
    __syncthreads();
    ln_rows8_512(h_sh, stat);
    float2 gv = ((const float2*)g1)[cp];
    float2 bev = ((const float2*)be1)[cp];
    float p0 = 0.f, p1 = 0.f;
    #pragma unroll
    for (int rr = 0; rr < 2; rr++) {
        int r = 2*rg + rr;
        float m = stat[r][0], is = stat[r][1];
        float t0 = (h_sh[r][2*cp]   - m) * is * gv.x + bev.x;
        float t1 = (h_sh[r][2*cp+1] - m) * is * gv.y + bev.y;
        float e0 = gelu_fast(t0), e1 = gelu_fast(t1);
        p0 += e0; p1 += e1;
        float2 st; st.x = e0; st.y = e1;
        ((float2*)(g_local + (row0 + r)*DD))[cp] = st;
    }
    part_sh[rg][2*cp] = p0;
    part_sh[rg][2*cp+1] = p1;
    __syncthreads();
    if (tid < 256)
        g_part[blockIdx.x*DD + tid] = part_sh[0][tid] + part_sh[1][tid] + part_sh[2][tid] + part_sh[3][tid];
}

// ---------------- K2: fused gfeat(2 blocks) + kNN + gather + spatial ----------------
__global__ void knn_spatial_kernel(const float* __restrict__ xyz, const float* __restrict__ Ws,
                                   const float* __restrict__ bs, const float* __restrict__ gs,
                                   const float* __restrict__ bes,
                                   const float* __restrict__ bg, const float* __restrict__ gg,
                                   const float* __restrict__ beg,
                                   float* __restrict__ out) {
    __shared__ __align__(16) float xs[NN*3];
    __shared__ float  d2s[NN];
    __shared__ __align__(16) float sPXY[NN*2];
    __shared__ __align__(16) float sPZR[NN*2];
    __shared__ __align__(16) float sIM[NN*2];
    __shared__ float  wV[8*KNN];
    __shared__ int    wI[8*KNN];
    __shared__ int    sel[KNN];
    __shared__ float  sums6[6];
    __shared__ float  red6[8][6];
    int tid = threadIdx.x;
    int lane = tid & 31, warp = tid >> 5;

    if (blockIdx.x < BB) {
        float* lm = xs;
        float* red = d2s;
        int b = blockIdx.x;
        float s = 0.f;
        #pragma unroll 16
        for (int blk = 0; blk < 64; blk++) s += g_part[(b*64 + blk)*DD + tid];
        lm[tid] = s * (1.0f/NN);
        __syncthreads();
        float acc = bg[tid];
        for (int kq = 0; kq < KQD; kq++) {
            float4 l4 = ((const float4*)lm)[kq];
            float4 w = g_Wgp[kq*DD + tid];
            acc = fmaf(l4.x, w.x, acc);
            acc = fmaf(l4.y, w.y, acc);
            acc = fmaf(l4.z, w.z, acc);
            acc = fmaf(l4.w, w.w, acc);
        }
        float sv = acc, s2 = acc*acc;
        #pragma unroll
        for (int o = 16; o > 0; o >>= 1) {
            sv += __shfl_down_sync(0xffffffffu, sv, o);
            s2 += __shfl_down_sync(0xffffffffu, s2, o);
        }
        if (lane == 0) { red[warp] = sv; red[8 + warp] = s2; }
        __syncthreads();
        float S = 0.f, S2 = 0.f;
        #pragma unroll
        for (int t = 0; t < 8; t++) { S += red[t]; S2 += red[8 + t]; }
        float m = S * (1.0f/DD);
        float is = rsqrtf(S2 * (1.0f/DD) - m*m + 1e-5f);
        g_gfeat[b*DD + tid] = (acc - m) * is * gg[tid] + beg[tid];
        return;
    }

    int bid = blockIdx.x - BB;
    int b = bid >> 9, i = bid & 511;
    for (int idx = tid; idx < NN*3; idx += 256) xs[idx] = xyz[b*NN*3 + idx];
    __syncthreads();
    float xi = xs[i*3], yi = xs[i*3+1], zi = xs[i*3+2];
    float lsx = 0.f, lsy = 0.f, lsz = 0.f, lsr = 0.f, lsi = 0.f, lsm = 0.f;
    #pragma unroll
    for (int jj = 0; jj < 2; jj++) {
        int j = tid + jj*256;
        float a = xi - xs[j*3], bc = yi - xs[j*3+1], c = zi - xs[j*3+2];
        float d2 = a*a + bc*bc + c*c;
        float rd = sqrtf(d2);
        d2s[j] = d2;
        float cf[5] = {a, bc, c, rd, 1.0f};
        float mm = fmaf(a, g_mu[0], fmaf(bc, g_mu[1], fmaf(c, g_mu[2], fmaf(rd, g_mu[3], g_mu[4]))));
        float var = 0.f;
        #pragma unroll
        for (int p = 0; p < 5; p++) {
            float t = 0.f;
            #pragma unroll
            for (int q = 0; q < 5; q++) t = fmaf(g_G[p*5 + q], cf[q], t);
            var = fmaf(cf[p], t, var);
        }
        float is = rsqrtf(var + 1e-5f);
        float px = is*a, py = is*bc, pz = is*c, pr = is*rd, pm = mm*is;
        int base = (j >> 1)*4 + (j & 1);
        sPXY[base]     = px;  sPXY[base + 2] = py;
        sPZR[base]     = pz;  sPZR[base + 2] = pr;
        sIM[base]      = is;  sIM[base + 2]  = pm;
        lsx += px; lsy += py; lsz += pz; lsr += pr; lsi += is; lsm += pm;
    }
    #pragma unroll
    for (int o = 16; o > 0; o >>= 1) {
        lsx += __shfl_down_sync(0xffffffffu, lsx, o);
        lsy += __shfl_down_sync(0xffffffffu, lsy, o);
        lsz += __shfl_down_sync(0xffffffffu, lsz, o);
        lsr += __shfl_down_sync(0xffffffffu, lsr, o);
        lsi += __shfl_down_sync(0xffffffffu, lsi, o);
        lsm += __shfl_down_sync(0xffffffffu, lsm, o);
    }
    if (lane == 0) {
        red6[warp][0] = lsx; red6[warp][1] = lsy; red6[warp][2] = lsz;
        red6[warp][3] = lsr; red6[warp][4] = lsi; red6[warp][5] = lsm;
    }
    __syncthreads();
    if (tid < 6) {
        float t = 0.f;
        #pragma unroll
        for (int w = 0; w < 8; w++) t += red6[w][tid];
        sums6[tid] = t;
    }
    {
        int j0 = warp*64 + lane, j1 = j0 + 32;
        float v0 = d2s[j0], v1 = d2s[j1];
        #pragma unroll
        for (int it = 0; it < KNN; it++) {
            float cv; int ci;
            if (v1 < v0) { cv = v1; ci = j1; } else { cv = v0; ci = j0; }
            #pragma unroll
            for (int o = 16; o > 0; o >>= 1) {
                float ov = __shfl_xor_sync(0xffffffffu, cv, o);
                int   oi = __shfl_xor_sync(0xffffffffu, ci, o);
                if (ov < cv || (ov == cv && oi < ci)) { cv = ov; ci = oi; }
            }
            if (lane == 0) { wV[warp*KNN + it] = cv; wI[warp*KNN + it] = ci; }
            if (ci == j0) v0 = 3.4e38f;
            if (ci == j1) v1 = 3.4e38f;
        }
    }
    __syncthreads();
    if (warp == 0) {
        float mv[4]; int mi[4];
        #pragma unroll
        for (int q = 0; q < 4; q++) { mv[q] = wV[q*32 + lane]; mi[q] = wI[q*32 + lane]; }
        #pragma unroll
        for (int it = 0; it < KNN; it++) {
            float cv = mv[0]; int ci = mi[0];
            #pragma unroll
            for (int q = 1; q < 4; q++)
                if (mv[q] < cv || (mv[q] == cv && mi[q] < ci)) { cv = mv[q]; ci = mi[q]; }
            #pragma unroll
            for (int o = 16; o > 0; o >>= 1) {
                float ov = __shfl_xor_sync(0xffffffffu, cv, o);
                int   oi = __shfl_xor_sync(0xffffffffu, ci, o);
                if (ov < cv || (ov == cv && oi < ci)) { cv = ov; ci = oi; }
            }
            if (lane == 0) sel[it] = ci;
            #pragma unroll
            for (int q = 0; q < 4; q++) if (mi[q] == ci) mv[q] = 3.4e38f;
        }
    }
    __syncthreads();
    float sg = 0.f;
    #pragma unroll
    for (int k = 0; k < KNN; k++) sg += g_local[(b*NN + sel[k])*DD + tid];
    g_regin[(b*NN + i)*DD + tid] = sg * (1.0f/KNN);
    float4 wv4 = *(const float4*)(Ws + tid*4);
    float gd = gs[tid], bed = bes[tid];
    float wxp = gd*wv4.x, wyp = gd*wv4.y, wzp = gd*wv4.z, wwp = gd*wv4.w;
    float bsp = gd*bs[tid];
    float sumT = wxp*sums6[0] + wyp*sums6[1] + wzp*sums6[2] + wwp*sums6[3]
               + bsp*sums6[4] - gd*sums6[5] + bed*(float)NN;
    const ull WX = pk2(wxp, wxp), WY = pk2(wyp, wyp);
    const ull WZ = pk2(wzp, wzp), WW = pk2(wwp, wwp);
    const ull BSP = pk2(bsp, bsp), NGD = pk2(-gd, -gd), BED = pk2(bed, bed);
    const ull ONE2  = pk2(1.0f, 1.0f);
    const ull ISQ2  = pk2(0.70710678118654752440f, 0.70710678118654752440f);
    const ull CP    = pk2(0.47047f, 0.47047f);
    const ull C3    = pk2(-0.7478556f, -0.7478556f);
    const ull C2    = pk2(0.0958798f, 0.0958798f);
    const ull C1    = pk2(-0.3480242f, -0.3480242f);
    const ull NL2E  = pk2(-1.4426950408889634f, -1.4426950408889634f);
    const ull ABSM  = 0x7FFFFFFF7FFFFFFFull;
    const ull SGNM  = 0x8000000080000000ull;
    const ulonglong2* pXY = (const ulonglong2*)sPXY;
    const ulonglong2* pZR = (const ulonglong2*)sPZR;
    const ulonglong2* pIM = (const ulonglong2*)sIM;
    ull acc2 = 0ull;
    #pragma unroll 2
    for (int j2 = 0; j2 < NN/2; j2++) {
        ulonglong2 axy = pXY[j2];
        ulonglong2 azr = pZR[j2];
        ulonglong2 aim = pIM[j2];
        ull t = f2fma(NGD, aim.y, BED);
        t = f2fma(BSP, aim.x, t);
        t = f2fma(WW, azr.y, t);
        t = f2fma(WZ, azr.x, t);
        t = f2fma(WY, axy.y, t);
        t = f2fma(WX, axy.x, t);
        ull xsp = f2mul(t, ISQ2);
        ull axp = xsp & ABSM;
        ull den = f2fma(axp, CP, ONE2);
        float2 dv = up2(den);
        ull tt = pk2(rcp_fast(dv.x), rcp_fast(dv.y));
        ull p = f2fma(C3, tt, C2);
        p = f2fma(p, tt, C1);
        p = f2mul(p, tt);
        ull m2 = f2mul(xsp, xsp);
        ull ea = f2mul(m2, NL2E);
        float2 ev = up2(ea);
        ull e2 = pk2(ex2_fast(ev.x), ex2_fast(ev.y));
        ull erf2 = f2fma(p, e2, ONE2);
        erf2 = erf2 | (xsp & SGNM);
        acc2 = f2fma(t, erf2, acc2);
    }
    float2 av = up2(acc2);
    out[(b*NN + i)*DD + tid] = 0.5f * (sumT + av.x + av.y) * (1.0f/NN);
}

// ---------------- K3: region MLP + combined + QKV (pipelined pair GEMMs) ----------------
__global__ void __launch_bounds__(512, 1) region_qkv_kernel(
        const float* __restrict__ br1, const float* __restrict__ gr1,
        const float* __restrict__ ber1, const float* __restrict__ br2,
        const float* __restrict__ gr2, const float* __restrict__ ber2,
        const float* __restrict__ bin_) {
    __shared__ __align__(16) ull in_dup[8][DD];
    __shared__ float h_sh[8][DD];
    __shared__ float stat[8][2];
    int row0 = blockIdx.x * 8;
    int b = row0 >> 9;
    int tid = threadIdx.x;
    int cp = tid & 127, rg = tid >> 7;
    for (int idx = tid; idx < 8*DD; idx += 512) {
        int r = idx >> 8, k = idx & 255;
        float v = g_regin[(row0 + r)*DD + k];
        in_dup[r][k] = pk2(v, v);
    }
    __syncthreads();
    const ulonglong2* ia = (const ulonglong2*)in_dup[2*rg];
    const ulonglong2* ib = (const ulonglong2*)in_dup[2*rg+1];
    ull acc0, acc1;
    { float2 bb = ((const float2*)br1)[cp]; acc0 = pk2(bb.x, bb.y); acc1 = acc0; }
    gemm_pair<KQD, 128>(g_Wr1v + cp, ia, ib, acc0, acc1);
    {
        float2 a = up2(acc0), bq = up2(acc1);
        ((float2*)h_sh[2*rg])[cp]   = a;
        ((float2*)h_sh[2*rg+1])[cp] = bq;
    }
    __syncthreads();
    ln_rows8_512(h_sh, stat);
    {
        float2 g1v = ((const float2*)gr1)[cp];
        float2 b1v = ((const float2*)ber1)[cp];
        #pragma unroll
        for (int rr = 0; rr < 2; rr++) {
            int r = 2*rg + rr;
            float m = stat[r][0], is = stat[r][1];
            float t0 = (h_sh[r][2*cp]   - m) * is * g1v.x + b1v.x;
            float t1 = (h_sh[r][2*cp+1] - m) * is * g1v.y + b1v.y;
            float e0 = gelu_fast(t0), e1 = gelu_fast(t1);
            in_dup[r][2*cp]   = pk2(e0, e0);
            in_dup[r][2*cp+1] = pk2(e1, e1);
        }
    }
    __syncthreads();
    { float2 bb = ((const float2*)br2)[cp]; acc0 = pk2(bb.x, bb.y); acc1 = acc0; }
    gemm_pair<KQD, 128>(g_Wr2v + cp, ia, ib, acc0, acc1);
    __syncthreads();   // all in_dup reads done before combined overwrite
    {
        float2 a = up2(acc0), bq = up2(acc1);
        ((float2*)h_sh[2*rg])[cp]   = a;
        ((float2*)h_sh[2*rg+1])[cp] = bq;
    }
    __syncthreads();
    ln_rows8_512(h_sh, stat);
    {
        float2 g2v = ((const float2*)gr2)[cp];
        float2 b2v = ((const float2*)ber2)[cp];
        float2 gf = ((const float2*)(g_gfeat + b*DD))[cp];
        #pragma unroll
        for (int rr = 0; rr < 2; rr++) {
            int r = 2*rg + rr;
            float m = stat[r][0], is = stat[r][1];
            float t0 = (h_sh[r][2*cp]   - m) * is * g2v.x + b2v.x;
            float t1 = (h_sh[r][2*cp+1] - m) * is * g2v.y + b2v.y;
            float2 lo = ((const float2*)(g_local + (row0 + r)*DD))[cp];
            float c0 = lo.x + t0 + gf.x;
            float c1 = lo.y + t1 + gf.y;
            in_dup[r][2*cp]   = pk2(c0, c0);
            in_dup[r][2*cp+1] = pk2(c1, c1);
        }
    }
    __syncthreads();
    // ---- QKV: 3 pipelined passes ----
    #pragma unroll
    for (int co = 0; co < 3; co++) {
        ull qa0, qa1;
        { float2 bb = ((const float2*)bin_)[co*128 + cp]; qa0 = pk2(bb.x, bb.y); qa1 = qa0; }
        gemm_pair<KQD, 384>(g_Winv + co*128 + cp, ia, ib, qa0, qa1);
        float2 a = up2(qa0), bq = up2(qa1);
        ((float2*)(g_qkv + (row0 + 2*rg)*QKVD + co*256))[cp]   = a;
        ((float2*)(g_qkv + (row0 + 2*rg+1)*QKVD + co*256))[cp] = bq;
    }
}

// ---------------- K4: attention split-KV, f32x2-packed ----------------
__global__ void attn_kernel() {
    __shared__ __align__(16) float Ksh[128][DH];
    __shared__ __align__(16) float Vsh[128][DH];
    int z = blockIdx.z;
    int b = z >> 2, s = z & 3;
    int h = blockIdx.y;
    int qi = blockIdx.x * 64 + threadIdx.x;
    int tid = threadIdx.x;
    const float scale = 0.17677669529663688f * 1.4426950408889634f;
    ull qp[16];
    const float* qrow = g_qkv + (b*NN + qi)*QKVD + h*DH;
    #pragma unroll
    for (int d4 = 0; d4 < 8; d4++) {
        float4 v = *(const float4*)(qrow + d4*4);
        qp[d4*2]   = pk2(v.x*scale, v.y*scale);
        qp[d4*2+1] = pk2(v.z*scale, v.w*scale);
    }
    int jt = s * 128;
    for (int idx = tid; idx < 128*DH; idx += 64) {
        int jj = idx >> 5, dd = idx & 31;
        int base = (b*NN + jt + jj)*QKVD + h*DH + dd;
        Ksh[jj][dd] = g_qkv[base + DD];
        Vsh[jj][dd] = g_qkv[base + 2*DD];
    }
    __syncthreads();
    float m = -1e30f, l = 0.f;
    ull op[16];
    #pragma unroll
    for (int t = 0; t < 16; t++) op[t] = 0ull;
    for (int jj = 0; jj < 128; jj++) {
        const ulonglong2* kp = (const ulonglong2*)Ksh[jj];
        ull s2a = 0ull, s2b = 0ull;
        #pragma unroll
        for (int t = 0; t < 8; t++) {
            ulonglong2 kv = kp[t];
            s2a = f2fma(qp[t*2],   kv.x, s2a);
            s2b = f2fma(qp[t*2+1], kv.y, s2b);
        }
        float2 sva = up2(s2a), svb = up2(s2b);
        float sc = (sva.x + sva.y) + (svb.x + svb.y);
        if (sc > m) {
            float corr = ex2_fast(m - sc);
            l *= corr;
            ull c2 = pk2(corr, corr);
            #pragma unroll
            for (int t = 0; t < 16; t++) op[t] = f2mul(op[t], c2);
            m = sc;
        }
        float p = ex2_fast(sc - m);
        l += p;
        ull pp = pk2(p, p);
        const ulonglong2* vp = (const ulonglong2*)Vsh[jj];
        #pragma unroll
        for (int t = 0; t < 8; t++) {
            ulonglong2 vv = vp[t];
            op[t*2]   = f2fma(pp, vv.x, op[t*2]);
            op[t*2+1] = f2fma(pp, vv.y, op[t*2+1]);
        }
    }
    int pb = ((b*NSPLIT + s)*HH + h)*NN + qi;
    g_pm[pb] = m;
    g_pl[pb] = l;
    float* po = g_po + pb*DH;
    #pragma unroll
    for (int t = 0; t < 16; t++) {
        float2 ov = up2(op[t]);
        po[t*2]   = ov.x;
        po[t*2+1] = ov.y;
    }
}

// ---------------- K5: merge splits + out += o @ Wo.T + bo ----------------
__global__ void __launch_bounds__(512, 1) oproj_kernel(const float* __restrict__ bo, float* __restrict__ out) {
    __shared__ float esc[8][HH][NSPLIT];
    __shared__ __align__(16) ull in_dup[8][DD];
    int row0 = blockIdx.x * 8;
    int b = row0 >> 9;
    int q0 = row0 & 511;
    int tid = threadIdx.x;
    int cp = tid & 127, rg = tid >> 7;
    if (tid < 64) {
        int r = tid >> 3, h = tid & 7;
        int q = q0 + r;
        float ms[NSPLIT];
        float mx = -1e30f;
        #pragma unroll
        for (int s = 0; s < NSPLIT; s++) {
            ms[s] = g_pm[((b*NSPLIT + s)*HH + h)*NN + q];
            mx = fmaxf(mx, ms[s]);
        }
        float lsum = 0.f;
        #pragma unroll
        for (int s = 0; s < NSPLIT; s++)
            lsum += g_pl[((b*NSPLIT + s)*HH + h)*NN + q] * ex2_fast(ms[s] - mx);
        float inv = 1.0f / lsum;
        #pragma unroll
        for (int s = 0; s < NSPLIT; s++)
            esc[r][h][s] = ex2_fast(ms[s] - mx) * inv;
    }
    __syncthreads();
    int ch0 = 2*cp;
    int h = ch0 >> 5, dh = ch0 & 31;
    #pragma unroll
    for (int rr = 0; rr < 2; rr++) {
        int r = 2*rg + rr;
        float o0 = 0.f, o1 = 0.f;
        #pragma unroll
        for (int s = 0; s < NSPLIT; s++) {
            const float2* base = (const float2*)(g_po + (((b*NSPLIT + s)*HH + h)*NN + q0 + r)*DH + dh);
            float2 pv = base[0];
            float e = esc[r][h][s];
            o0 = fmaf(pv.x, e, o0);
            o1 = fmaf(pv.y, e, o1);
        }
        in_dup[r][ch0]   = pk2(o0, o0);
        in_dup[r][ch0+1] = pk2(o1, o1);
    }
    __syncthreads();
    ull acc0, acc1;
    { float2 bb = ((const float2*)bo)[cp]; acc0 = pk2(bb.x, bb.y); acc1 = acc0; }
    gemm_pair<KQD, 128>(g_Wov + cp,
                        (const ulonglong2*)in_dup[2*rg],
                        (const ulonglong2*)in_dup[2*rg+1], acc0, acc1);
    {
        float2 a = up2(acc0), bq = up2(acc1);
        float2* o0p = (float2*)(out + (row0 + 2*rg)*DD) + cp;
        float2* o1p = (float2*)(out + (row0 + 2*rg+1)*DD) + cp;
        float2 v0 = *o0p, v1 = *o1p;
        v0.x += a.x;  v0.y += a.y;
        v1.x += bq.x; v1.y += bq.y;
        *o0p = v0; *o1p = v1;
    }
}

// ---------------- launch ----------------
extern "C" void kernel_launch(void* const* d_in, const int* in_sizes, int n_in,
                              void* d_out, int out_size) {
    const float* x    = (const float*)d_in[0];
    const float* pf   = (const float*)d_in[1];
    const float* xyz  = (const float*)d_in[2];
    const float* W1   = (const float*)d_in[3];
    const float* b1   = (const float*)d_in[4];
    const float* g1   = (const float*)d_in[5];
    const float* be1  = (const float*)d_in[6];
    const float* Wr1  = (const float*)d_in[7];
    const float* br1  = (const float*)d_in[8];
    const float* gr1  = (const float*)d_in[9];
    const float* ber1 = (const float*)d_in[10];
    const float* Wr2  = (const float*)d_in[11];
    const float* br2  = (const float*)d_in[12];
    const float* gr2  = (const float*)d_in[13];
    const float* ber2 = (const float*)d_in[14];
    const float* Wg   = (const float*)d_in[15];
    const float* bg   = (const float*)d_in[16];
    const float* gg   = (const float*)d_in[17];
    const float* beg  = (const float*)d_in[18];
    const float* Win  = (const float*)d_in[19];
    const float* bin_ = (const float*)d_in[20];
    const float* Wo   = (const float*)d_in[21];
    const float* bo   = (const float*)d_in[22];
    const float* Ws   = (const float*)d_in[23];
    const float* bs   = (const float*)d_in[24];
    const float* gs   = (const float*)d_in[25];
    const float* bes  = (const float*)d_in[26];
    float* out = (float*)d_out;

    prep_gram_kernel<<<NPREP + 1, 256>>>(W1, Wr1, Wr2, Win, Wo, Wg, Ws, bs);
    local_encoder_kernel<<<128, 512>>>(x, pf, xyz, b1, g1, be1);
    knn_spatial_kernel<<<BB*NN + BB, 256>>>(xyz, Ws, bs, gs, bes, bg, gg, beg, out);
    region_qkv_kernel<<<128, 512>>>(br1, gr1, ber1, br2, gr2, ber2, bin_);
    dim3 ag(NN/64, HH, BB*NSPLIT);
    attn_kernel<<<ag, 64>>>();
    oproj_kernel<<<128, 512>>>(bo, out);
}

// round 11
// speedup vs baseline: 2.1412x; 1.5379x over previous
#include <cuda_runtime.h>
#include <math.h>

#define BB 2
#define NN 512
#define CD 64
#define PF 128
#define DD 256
#define KNN 16
#define HH 8
#define DH 32
#define QKVD 768
#define CIN 195
#define KQ1P 52     // padded ceil(195/4) -> 52 kq = 208 k
#define KQD 64      // 256/4
#define NSPLIT 4

typedef unsigned long long ull;

// ---------------- scratch (device globals) ----------------
// pair-packed weights: [kh2 * NCP + cp] ulonglong2, .x=(w[2cp][2kh2],w[2cp+1][2kh2]), .y=same k+1
__device__ ulonglong2 g_W1v[104*128];
__device__ ulonglong2 g_Wr1v[128*128];
__device__ ulonglong2 g_Wr2v[128*128];
__device__ ulonglong2 g_Wov[128*128];
__device__ ulonglong2 g_Winv[128*384];
__device__ float4 g_Wgp[KQD*DD];
__device__ float g_mu[5];
__device__ float g_G[25];
__device__ __align__(16) float g_local[BB*NN*DD];
__device__ __align__(16) float g_regin[BB*NN*DD];
__device__ __align__(16) float g_qkv[BB*NN*QKVD];
__device__ float g_part[128*DD];
__device__ float g_gfeat[BB*DD];
__device__ float g_pm[BB*NSPLIT*HH*NN];
__device__ float g_pl[BB*NSPLIT*HH*NN];
__device__ __align__(16) float g_po[BB*NSPLIT*HH*NN*DH];

// ---------------- f32x2 packed math ----------------
__device__ __forceinline__ ull f2fma(ull a, ull b, ull c){ ull d; asm("fma.rn.f32x2 %0, %1, %2, %3;" : "=l"(d) : "l"(a), "l"(b), "l"(c)); return d; }
__device__ __forceinline__ ull f2mul(ull a, ull b){ ull d; asm("mul.rn.f32x2 %0, %1, %2;" : "=l"(d) : "l"(a), "l"(b)); return d; }
__device__ __forceinline__ ull pk2(float lo, float hi){ ull r; asm("mov.b64 %0, {%1,%2};" : "=l"(r) : "f"(lo), "f"(hi)); return r; }
__device__ __forceinline__ float2 up2(ull v){ float2 r; asm("mov.b64 {%0,%1}, %2;" : "=f"(r.x), "=f"(r.y) : "l"(v)); return r; }
__device__ __forceinline__ float rcp_fast(float x){ float r; asm("rcp.approx.ftz.f32 %0, %1;" : "=f"(r) : "f"(x)); return r; }
__device__ __forceinline__ float ex2_fast(float x){ float r; asm("ex2.approx.ftz.f32 %0, %1;" : "=f"(r) : "f"(x)); return r; }

__device__ __forceinline__ float gelu_fast(float x) {
    float xs = x * 0.70710678118654752440f;
    float ax = fabsf(xs);
    float t  = rcp_fast(fmaf(0.3275911f, ax, 1.0f));
    float p  = t * fmaf(t, fmaf(t, fmaf(t, fmaf(t, 1.061405429f, -1.453152027f),
                       1.421413741f), -0.284496736f), 0.254829592f);
    float e  = ex2_fast(-xs * xs * 1.4426950408889634f);
    float erfv = fmaf(-p, e, 1.0f);
    erfv = copysignf(erfv, xs);
    return 0.5f * x * (1.0f + erfv);
}

// ---------------- pair-GEMM core: bounded liveness, ptxas-scheduled ----------------
// Plain unroll-4 loop: per kq, 2 LDG.128 (pair-packed weights), 4 LDS.128, 8 FFMA2.
// No manual prefetch chains -> ptxas batches loads within each unrolled body
// while keeping register liveness bounded (R7-proven compile shape).
template<int NKQ, int WS>
__device__ __forceinline__ void gemm_pair(const ulonglong2* __restrict__ wp,
                                          const ulonglong2* __restrict__ ia,
                                          const ulonglong2* __restrict__ ib,
                                          ull& acc0, ull& acc1) {
    #pragma unroll 4
    for (int kq = 0; kq < NKQ; kq++) {
        ulonglong2 w0 = wp[(2*kq)*WS];
        ulonglong2 w1 = wp[(2*kq+1)*WS];
        ulonglong2 a0 = ia[2*kq], a1 = ia[2*kq+1];
        ulonglong2 b0 = ib[2*kq], b1 = ib[2*kq+1];
        acc0 = f2fma(w0.x, a0.x, acc0); acc0 = f2fma(w0.y, a0.y, acc0);
        acc0 = f2fma(w1.x, a1.x, acc0); acc0 = f2fma(w1.y, a1.y, acc0);
        acc1 = f2fma(w0.x, b0.x, acc1); acc1 = f2fma(w0.y, b0.y, acc1);
        acc1 = f2fma(w1.x, b1.x, acc1); acc1 = f2fma(w1.y, b1.y, acc1);
    }
}

// ---------------- K0: weight packing + 5x5 Gram ----------------
__device__ __forceinline__ float blockSumAll(float v, float* red) {
    #pragma unroll
    for (int o = 16; o > 0; o >>= 1) v += __shfl_down_sync(0xffffffffu, v, o);
    int w = threadIdx.x >> 5, l = threadIdx.x & 31;
    __syncthreads();
    if (l == 0) red[w] = v;
    __syncthreads();
    return red[0]+red[1]+red[2]+red[3]+red[4]+red[5]+red[6]+red[7];
}

#define NPREP 64
__global__ void prep_gram_kernel(const float* __restrict__ W1, const float* __restrict__ Wr1,
                                 const float* __restrict__ Wr2, const float* __restrict__ Win,
                                 const float* __restrict__ Wo, const float* __restrict__ Wg,
                                 const float* __restrict__ Ws, const float* __restrict__ bs) {
    if (blockIdx.x < NPREP) {
        int i = blockIdx.x * 256 + threadIdx.x;
        int stride = NPREP * 256;
        // W1 pair-pack (padded k)
        for (int e = i; e < 104*128; e += stride) {
            int kh2 = e >> 7, cp = e & 127;
            int k = 2*kh2;
            int c0 = 2*cp, c1 = 2*cp + 1;
            float w00 = (k   < CIN) ? W1[c0*CIN + k]   : 0.f;
            float w10 = (k   < CIN) ? W1[c1*CIN + k]   : 0.f;
            float w01 = (k+1 < CIN) ? W1[c0*CIN + k+1] : 0.f;
            float w11 = (k+1 < CIN) ? W1[c1*CIN + k+1] : 0.f;
            ulonglong2 v; v.x = pk2(w00, w10); v.y = pk2(w01, w11);
            g_W1v[e] = v;
        }
        // DD x DD matrices pair-pack
        for (int e = i; e < 128*128; e += stride) {
            int kh2 = e >> 7, cp = e & 127;
            int k = 2*kh2;
            int c0 = 2*cp, c1 = 2*cp + 1;
            ulonglong2 v;
            v.x = pk2(Wr1[c0*DD + k],   Wr1[c1*DD + k]);
            v.y = pk2(Wr1[c0*DD + k+1], Wr1[c1*DD + k+1]);
            g_Wr1v[e] = v;
            v.x = pk2(Wr2[c0*DD + k],   Wr2[c1*DD + k]);
            v.y = pk2(Wr2[c0*DD + k+1], Wr2[c1*DD + k+1]);
            g_Wr2v[e] = v;
            v.x = pk2(Wo[c0*DD + k],    Wo[c1*DD + k]);
            v.y = pk2(Wo[c0*DD + k+1],  Wo[c1*DD + k+1]);
            g_Wov[e] = v;
        }
        // Win pair-pack: cp global 0..383
        for (int e = i; e < 128*384; e += stride) {
            int kh2 = e / 384, cp = e % 384;
            int k = 2*kh2;
            int c0 = 2*cp, c1 = 2*cp + 1;
            ulonglong2 v;
            v.x = pk2(Win[c0*DD + k],   Win[c1*DD + k]);
            v.y = pk2(Win[c0*DD + k+1], Win[c1*DD + k+1]);
            g_Winv[e] = v;
        }
        // Wg float4 pack (gfeat path)
        for (int e = i; e < DD*KQD; e += stride) {
            int d = e >> 6, kq = e & 63;
            g_Wgp[kq*DD + d] = ((const float4*)(Wg + d*DD))[kq];
        }
    } else {
        __shared__ float red[8];
        int d = threadIdx.x;
        float4 w4 = *(const float4*)(Ws + d*4);
        float v[5] = {w4.x, w4.y, w4.z, w4.w, bs[d]};
        float mu[5];
        #pragma unroll
        for (int p = 0; p < 5; p++) mu[p] = blockSumAll(v[p], red) * (1.0f/DD);
        #pragma unroll
        for (int p = 0; p < 5; p++) v[p] -= mu[p];
        for (int p = 0; p < 5; p++)
            for (int q = 0; q < 5; q++) {
                float s = blockSumAll(v[p]*v[q], red) * (1.0f/DD);
                if (d == 0) g_G[p*5 + q] = s;
            }
        if (d == 0) { for (int p = 0; p < 5; p++) g_mu[p] = mu[p]; }
    }
}

// ---------------- LN stats for 8 rows (512-thread blocks) ----------------
__device__ __forceinline__ void ln_rows8_512(float (*h_sh)[DD], float (*stat)[2]) {
    int w = threadIdx.x >> 5, l = threadIdx.x & 31;
    if (w < 8) {
        float s = 0.f, s2 = 0.f;
        #pragma unroll
        for (int i = l; i < DD; i += 32) { float v = h_sh[w][i]; s += v; s2 += v*v; }
        #pragma unroll
        for (int o = 16; o > 0; o >>= 1) {
            s  += __shfl_down_sync(0xffffffffu, s,  o);
            s2 += __shfl_down_sync(0xffffffffu, s2, o);
        }
        if (l == 0) {
            float m = s * (1.0f/DD);
            stat[w][0] = m;
            stat[w][1] = rsqrtf(s2 * (1.0f/DD) - m*m + 1e-5f);
        }
    }
    __syncthreads();
}

// ---------------- K1: local encoder ----------------
__global__ void __launch_bounds__(512) local_encoder_kernel(
        const float* __restrict__ x, const float* __restrict__ pf,
        const float* __restrict__ xyz, const float* __restrict__ b1,
        const float* __restrict__ g1, const float* __restrict__ be1) {
    __shared__ __align__(16) ull in_dup[8][208];
    __shared__ float h_sh[8][DD];
    __shared__ float stat[8][2];
    __shared__ float part_sh[4][DD];
    int row0 = blockIdx.x * 8;
    int tid = threadIdx.x;
    int cp = tid & 127, rg = tid >> 7;   // rows 2rg, 2rg+1
    for (int idx = tid; idx < 8*208; idx += 512) {
        int r = idx / 208, k = idx % 208, row = row0 + r;
        float v;
        if (k < CD)          v = x[row*CD + k];
        else if (k < CD+PF)  v = pf[row*PF + (k - CD)];
        else if (k < CIN)    v = xyz[row*3 + (k - CD - PF)];
        else                 v = 0.f;
        in_dup[r][k] = pk2(v, v);
    }
    __syncthreads();
    ull acc0, acc1;
    { float2 bb = ((const float2*)b1)[cp]; acc0 = pk2(bb.x, bb.y); acc1 = acc0; }
    gemm_pair<KQ1P, 128>(g_W1v + cp,
                         (const ulonglong2*)in_dup[2*rg],
                         (const ulonglong2*)in_dup[2*rg+1], acc0, acc1);
    {
        float2 a = up2(acc0), b = up2(acc1);
        ((float2*)h_sh[2*rg])[cp]   = a;
        ((float2*)h_sh[2*rg+1])[cp] = b;
    }
    __syncthreads();
    ln_rows8_512(h_sh, stat);
    float2 gv = ((const float2*)g1)[cp];
    float2 bev = ((const float2*)be1)[cp];
    float p0 = 0.f, p1 = 0.f;
    #pragma unroll
    for (int rr = 0; rr < 2; rr++) {
        int r = 2*rg + rr;
        float m = stat[r][0], is = stat[r][1];
        float t0 = (h_sh[r][2*cp]   - m) * is * gv.x + bev.x;
        float t1 = (h_sh[r][2*cp+1] - m) * is * gv.y + bev.y;
        float e0 = gelu_fast(t0), e1 = gelu_fast(t1);
        p0 += e0; p1 += e1;
        float2 st; st.x = e0; st.y = e1;
        ((float2*)(g_local + (row0 + r)*DD))[cp] = st;
    }
    part_sh[rg][2*cp] = p0;
    part_sh[rg][2*cp+1] = p1;
    __syncthreads();
    if (tid < 256)
        g_part[blockIdx.x*DD + tid] = part_sh[0][tid] + part_sh[1][tid] + part_sh[2][tid] + part_sh[3][tid];
}

// ---------------- K2: fused gfeat(2 blocks) + kNN + gather + spatial ----------------
__global__ void knn_spatial_kernel(const float* __restrict__ xyz, const float* __restrict__ Ws,
                                   const float* __restrict__ bs, const float* __restrict__ gs,
                                   const float* __restrict__ bes,
                                   const float* __restrict__ bg, const float* __restrict__ gg,
                                   const float* __restrict__ beg,
                                   float* __restrict__ out) {
    __shared__ __align__(16) float xs[NN*3];
    __shared__ float  d2s[NN];
    __shared__ __align__(16) float sPXY[NN*2];
    __shared__ __align__(16) float sPZR[NN*2];
    __shared__ __align__(16) float sIM[NN*2];
    __shared__ float  wV[8*KNN];
    __shared__ int    wI[8*KNN];
    __shared__ int    sel[KNN];
    __shared__ float  sums6[6];
    __shared__ float  red6[8][6];
    int tid = threadIdx.x;
    int lane = tid & 31, warp = tid >> 5;

    if (blockIdx.x < BB) {
        float* lm = xs;
        float* red = d2s;
        int b = blockIdx.x;
        float s = 0.f;
        #pragma unroll 16
        for (int blk = 0; blk < 64; blk++) s += g_part[(b*64 + blk)*DD + tid];
        lm[tid] = s * (1.0f/NN);
        __syncthreads();
        float acc = bg[tid];
        for (int kq = 0; kq < KQD; kq++) {
            float4 l4 = ((const float4*)lm)[kq];
            float4 w = g_Wgp[kq*DD + tid];
            acc = fmaf(l4.x, w.x, acc);
            acc = fmaf(l4.y, w.y, acc);
            acc = fmaf(l4.z, w.z, acc);
            acc = fmaf(l4.w, w.w, acc);
        }
        float sv = acc, s2 = acc*acc;
        #pragma unroll
        for (int o = 16; o > 0; o >>= 1) {
            sv += __shfl_down_sync(0xffffffffu, sv, o);
            s2 += __shfl_down_sync(0xffffffffu, s2, o);
        }
        if (lane == 0) { red[warp] = sv; red[8 + warp] = s2; }
        __syncthreads();
        float S = 0.f, S2 = 0.f;
        #pragma unroll
        for (int t = 0; t < 8; t++) { S += red[t]; S2 += red[8 + t]; }
        float m = S * (1.0f/DD);
        float is = rsqrtf(S2 * (1.0f/DD) - m*m + 1e-5f);
        g_gfeat[b*DD + tid] = (acc - m) * is * gg[tid] + beg[tid];
        return;
    }

    int bid = blockIdx.x - BB;
    int b = bid >> 9, i = bid & 511;
    for (int idx = tid; idx < NN*3; idx += 256) xs[idx] = xyz[b*NN*3 + idx];
    __syncthreads();
    float xi = xs[i*3], yi = xs[i*3+1], zi = xs[i*3+2];
    float lsx = 0.f, lsy = 0.f, lsz = 0.f, lsr = 0.f, lsi = 0.f, lsm = 0.f;
    #pragma unroll
    for (int jj = 0; jj < 2; jj++) {
        int j = tid + jj*256;
        float a = xi - xs[j*3], bc = yi - xs[j*3+1], c = zi - xs[j*3+2];
        float d2 = a*a + bc*bc + c*c;
        float rd = sqrtf(d2);
        d2s[j] = d2;
        float cf[5] = {a, bc, c, rd, 1.0f};
        float mm = fmaf(a, g_mu[0], fmaf(bc, g_mu[1], fmaf(c, g_mu[2], fmaf(rd, g_mu[3], g_mu[4]))));
        float var = 0.f;
        #pragma unroll
        for (int p = 0; p < 5; p++) {
            float t = 0.f;
            #pragma unroll
            for (int q = 0; q < 5; q++) t = fmaf(g_G[p*5 + q], cf[q], t);
            var = fmaf(cf[p], t, var);
        }
        float is = rsqrtf(var + 1e-5f);
        float px = is*a, py = is*bc, pz = is*c, pr = is*rd, pm = mm*is;
        int base = (j >> 1)*4 + (j & 1);
        sPXY[base]     = px;  sPXY[base + 2] = py;
        sPZR[base]     = pz;  sPZR[base + 2] = pr;
        sIM[base]      = is;  sIM[base + 2]  = pm;
        lsx += px; lsy += py; lsz += pz; lsr += pr; lsi += is; lsm += pm;
    }
    #pragma unroll
    for (int o = 16; o > 0; o >>= 1) {
        lsx += __shfl_down_sync(0xffffffffu, lsx, o);
        lsy += __shfl_down_sync(0xffffffffu, lsy, o);
        lsz += __shfl_down_sync(0xffffffffu, lsz, o);
        lsr += __shfl_down_sync(0xffffffffu, lsr, o);
        lsi += __shfl_down_sync(0xffffffffu, lsi, o);
        lsm += __shfl_down_sync(0xffffffffu, lsm, o);
    }
    if (lane == 0) {
        red6[warp][0] = lsx; red6[warp][1] = lsy; red6[warp][2] = lsz;
        red6[warp][3] = lsr; red6[warp][4] = lsi; red6[warp][5] = lsm;
    }
    __syncthreads();
    if (tid < 6) {
        float t = 0.f;
        #pragma unroll
        for (int w = 0; w < 8; w++) t += red6[w][tid];
        sums6[tid] = t;
    }
    {
        int j0 = warp*64 + lane, j1 = j0 + 32;
        float v0 = d2s[j0], v1 = d2s[j1];
        #pragma unroll
        for (int it = 0; it < KNN; it++) {
            float cv; int ci;
            if (v1 < v0) { cv = v1; ci = j1; } else { cv = v0; ci = j0; }
            #pragma unroll
            for (int o = 16; o > 0; o >>= 1) {
                float ov = __shfl_xor_sync(0xffffffffu, cv, o);
                int   oi = __shfl_xor_sync(0xffffffffu, ci, o);
                if (ov < cv || (ov == cv && oi < ci)) { cv = ov; ci = oi; }
            }
            if (lane == 0) { wV[warp*KNN + it] = cv; wI[warp*KNN + it] = ci; }
            if (ci == j0) v0 = 3.4e38f;
            if (ci == j1) v1 = 3.4e38f;
        }
    }
    __syncthreads();
    if (warp == 0) {
        float mv[4]; int mi[4];
        #pragma unroll
        for (int q = 0; q < 4; q++) { mv[q] = wV[q*32 + lane]; mi[q] = wI[q*32 + lane]; }
        #pragma unroll
        for (int it = 0; it < KNN; it++) {
            float cv = mv[0]; int ci = mi[0];
            #pragma unroll
            for (int q = 1; q < 4; q++)
                if (mv[q] < cv || (mv[q] == cv && mi[q] < ci)) { cv = mv[q]; ci = mi[q]; }
            #pragma unroll
            for (int o = 16; o > 0; o >>= 1) {
                float ov = __shfl_xor_sync(0xffffffffu, cv, o);
                int   oi = __shfl_xor_sync(0xffffffffu, ci, o);
                if (ov < cv || (ov == cv && oi < ci)) { cv = ov; ci = oi; }
            }
            if (lane == 0) sel[it] = ci;
            #pragma unroll
            for (int q = 0; q < 4; q++) if (mi[q] == ci) mv[q] = 3.4e38f;
        }
    }
    __syncthreads();
    float sg = 0.f;
    #pragma unroll
    for (int k = 0; k < KNN; k++) sg += g_local[(b*NN + sel[k])*DD + tid];
    g_regin[(b*NN + i)*DD + tid] = sg * (1.0f/KNN);
    float4 wv4 = *(const float4*)(Ws + tid*4);
    float gd = gs[tid], bed = bes[tid];
    float wxp = gd*wv4.x, wyp = gd*wv4.y, wzp = gd*wv4.z, wwp = gd*wv4.w;
    float bsp = gd*bs[tid];
    float sumT = wxp*sums6[0] + wyp*sums6[1] + wzp*sums6[2] + wwp*sums6[3]
               + bsp*sums6[4] - gd*sums6[5] + bed*(float)NN;
    const ull WX = pk2(wxp, wxp), WY = pk2(wyp, wyp);
    const ull WZ = pk2(wzp, wzp), WW = pk2(wwp, wwp);
    const ull BSP = pk2(bsp, bsp), NGD = pk2(-gd, -gd), BED = pk2(bed, bed);
    const ull ONE2  = pk2(1.0f, 1.0f);
    const ull ISQ2  = pk2(0.70710678118654752440f, 0.70710678118654752440f);
    const ull CP    = pk2(0.47047f, 0.47047f);
    const ull C3    = pk2(-0.7478556f, -0.7478556f);
    const ull C2    = pk2(0.0958798f, 0.0958798f);
    const ull C1    = pk2(-0.3480242f, -0.3480242f);
    const ull NL2E  = pk2(-1.4426950408889634f, -1.4426950408889634f);
    const ull ABSM  = 0x7FFFFFFF7FFFFFFFull;
    const ull SGNM  = 0x8000000080000000ull;
    const ulonglong2* pXY = (const ulonglong2*)sPXY;
    const ulonglong2* pZR = (const ulonglong2*)sPZR;
    const ulonglong2* pIM = (const ulonglong2*)sIM;
    ull acc2 = 0ull;
    #pragma unroll 2
    for (int j2 = 0; j2 < NN/2; j2++) {
        ulonglong2 axy = pXY[j2];
        ulonglong2 azr = pZR[j2];
        ulonglong2 aim = pIM[j2];
        ull t = f2fma(NGD, aim.y, BED);
        t = f2fma(BSP, aim.x, t);
        t = f2fma(WW, azr.y, t);
        t = f2fma(WZ, azr.x, t);
        t = f2fma(WY, axy.y, t);
        t = f2fma(WX, axy.x, t);
        ull xsp = f2mul(t, ISQ2);
        ull axp = xsp & ABSM;
        ull den = f2fma(axp, CP, ONE2);
        float2 dv = up2(den);
        ull tt = pk2(rcp_fast(dv.x), rcp_fast(dv.y));
        ull p = f2fma(C3, tt, C2);
        p = f2fma(p, tt, C1);
        p = f2mul(p, tt);
        ull m2 = f2mul(xsp, xsp);
        ull ea = f2mul(m2, NL2E);
        float2 ev = up2(ea);
        ull e2 = pk2(ex2_fast(ev.x), ex2_fast(ev.y));
        ull erf2 = f2fma(p, e2, ONE2);
        erf2 = erf2 | (xsp & SGNM);
        acc2 = f2fma(t, erf2, acc2);
    }
    float2 av = up2(acc2);
    out[(b*NN + i)*DD + tid] = 0.5f * (sumT + av.x + av.y) * (1.0f/NN);
}

// ---------------- K3: region MLP + combined + QKV (pair GEMMs) ----------------
__global__ void __launch_bounds__(512) region_qkv_kernel(
        const float* __restrict__ br1, const float* __restrict__ gr1,
        const float* __restrict__ ber1, const float* __restrict__ br2,
        const float* __restrict__ gr2, const float* __restrict__ ber2,
        const float* __restrict__ bin_) {
    __shared__ __align__(16) ull in_dup[8][DD];
    __shared__ float h_sh[8][DD];
    __shared__ float stat[8][2];
    int row0 = blockIdx.x * 8;
    int b = row0 >> 9;
    int tid = threadIdx.x;
    int cp = tid & 127, rg = tid >> 7;
    for (int idx = tid; idx < 8*DD; idx += 512) {
        int r = idx >> 8, k = idx & 255;
        float v = g_regin[(row0 + r)*DD + k];
        in_dup[r][k] = pk2(v, v);
    }
    __syncthreads();
    const ulonglong2* ia = (const ulonglong2*)in_dup[2*rg];
    const ulonglong2* ib = (const ulonglong2*)in_dup[2*rg+1];
    ull acc0, acc1;
    { float2 bb = ((const float2*)br1)[cp]; acc0 = pk2(bb.x, bb.y); acc1 = acc0; }
    gemm_pair<KQD, 128>(g_Wr1v + cp, ia, ib, acc0, acc1);
    {
        float2 a = up2(acc0), bq = up2(acc1);
        ((float2*)h_sh[2*rg])[cp]   = a;
        ((float2*)h_sh[2*rg+1])[cp] = bq;
    }
    __syncthreads();
    ln_rows8_512(h_sh, stat);
    {
        float2 g1v = ((const float2*)gr1)[cp];
        float2 b1v = ((const float2*)ber1)[cp];
        #pragma unroll
        for (int rr = 0; rr < 2; rr++) {
            int r = 2*rg + rr;
            float m = stat[r][0], is = stat[r][1];
            float t0 = (h_sh[r][2*cp]   - m) * is * g1v.x + b1v.x;
            float t1 = (h_sh[r][2*cp+1] - m) * is * g1v.y + b1v.y;
            float e0 = gelu_fast(t0), e1 = gelu_fast(t1);
            in_dup[r][2*cp]   = pk2(e0, e0);
            in_dup[r][2*cp+1] = pk2(e1, e1);
        }
    }
    __syncthreads();
    { float2 bb = ((const float2*)br2)[cp]; acc0 = pk2(bb.x, bb.y); acc1 = acc0; }
    gemm_pair<KQD, 128>(g_Wr2v + cp, ia, ib, acc0, acc1);
    __syncthreads();   // all in_dup reads done before combined overwrite
    {
        float2 a = up2(acc0), bq = up2(acc1);
        ((float2*)h_sh[2*rg])[cp]   = a;
        ((float2*)h_sh[2*rg+1])[cp] = bq;
    }
    __syncthreads();
    ln_rows8_512(h_sh, stat);
    {
        float2 g2v = ((const float2*)gr2)[cp];
        float2 b2v = ((const float2*)ber2)[cp];
        float2 gf = ((const float2*)(g_gfeat + b*DD))[cp];
        #pragma unroll
        for (int rr = 0; rr < 2; rr++) {
            int r = 2*rg + rr;
            float m = stat[r][0], is = stat[r][1];
            float t0 = (h_sh[r][2*cp]   - m) * is * g2v.x + b2v.x;
            float t1 = (h_sh[r][2*cp+1] - m) * is * g2v.y + b2v.y;
            float2 lo = ((const float2*)(g_local + (row0 + r)*DD))[cp];
            float c0 = lo.x + t0 + gf.x;
            float c1 = lo.y + t1 + gf.y;
            in_dup[r][2*cp]   = pk2(c0, c0);
            in_dup[r][2*cp+1] = pk2(c1, c1);
        }
    }
    __syncthreads();
    // ---- QKV: 3 passes ----
    #pragma unroll
    for (int co = 0; co < 3; co++) {
        ull qa0, qa1;
        { float2 bb = ((const float2*)bin_)[co*128 + cp]; qa0 = pk2(bb.x, bb.y); qa1 = qa0; }
        gemm_pair<KQD, 384>(g_Winv + co*128 + cp, ia, ib, qa0, qa1);
        float2 a = up2(qa0), bq = up2(qa1);
        ((float2*)(g_qkv + (row0 + 2*rg)*QKVD + co*256))[cp]   = a;
        ((float2*)(g_qkv + (row0 + 2*rg+1)*QKVD + co*256))[cp] = bq;
    }
}

// ---------------- K4: attention split-KV, f32x2-packed ----------------
__global__ void attn_kernel() {
    __shared__ __align__(16) float Ksh[128][DH];
    __shared__ __align__(16) float Vsh[128][DH];
    int z = blockIdx.z;
    int b = z >> 2, s = z & 3;
    int h = blockIdx.y;
    int qi = blockIdx.x * 64 + threadIdx.x;
    int tid = threadIdx.x;
    const float scale = 0.17677669529663688f * 1.4426950408889634f;
    ull qp[16];
    const float* qrow = g_qkv + (b*NN + qi)*QKVD + h*DH;
    #pragma unroll
    for (int d4 = 0; d4 < 8; d4++) {
        float4 v = *(const float4*)(qrow + d4*4);
        qp[d4*2]   = pk2(v.x*scale, v.y*scale);
        qp[d4*2+1] = pk2(v.z*scale, v.w*scale);
    }
    int jt = s * 128;
    for (int idx = tid; idx < 128*DH; idx += 64) {
        int jj = idx >> 5, dd = idx & 31;
        int base = (b*NN + jt + jj)*QKVD + h*DH + dd;
        Ksh[jj][dd] = g_qkv[base + DD];
        Vsh[jj][dd] = g_qkv[base + 2*DD];
    }
    __syncthreads();
    float m = -1e30f, l = 0.f;
    ull op[16];
    #pragma unroll
    for (int t = 0; t < 16; t++) op[t] = 0ull;
    for (int jj = 0; jj < 128; jj++) {
        const ulonglong2* kp = (const ulonglong2*)Ksh[jj];
        ull s2a = 0ull, s2b = 0ull;
        #pragma unroll
        for (int t = 0; t < 8; t++) {
            ulonglong2 kv = kp[t];
            s2a = f2fma(qp[t*2],   kv.x, s2a);
            s2b = f2fma(qp[t*2+1], kv.y, s2b);
        }
        float2 sva = up2(s2a), svb = up2(s2b);
        float sc = (sva.x + sva.y) + (svb.x + svb.y);
        if (sc > m) {
            float corr = ex2_fast(m - sc);
            l *= corr;
            ull c2 = pk2(corr, corr);
            #pragma unroll
            for (int t = 0; t < 16; t++) op[t] = f2mul(op[t], c2);
            m = sc;
        }
        float p = ex2_fast(sc - m);
        l += p;
        ull pp = pk2(p, p);
        const ulonglong2* vp = (const ulonglong2*)Vsh[jj];
        #pragma unroll
        for (int t = 0; t < 8; t++) {
            ulonglong2 vv = vp[t];
            op[t*2]   = f2fma(pp, vv.x, op[t*2]);
            op[t*2+1] = f2fma(pp, vv.y, op[t*2+1]);
        }
    }
    int pb = ((b*NSPLIT + s)*HH + h)*NN + qi;
    g_pm[pb] = m;
    g_pl[pb] = l;
    float* po = g_po + pb*DH;
    #pragma unroll
    for (int t = 0; t < 16; t++) {
        float2 ov = up2(op[t]);
        po[t*2]   = ov.x;
        po[t*2+1] = ov.y;
    }
}

// ---------------- K5: merge splits + out += o @ Wo.T + bo ----------------
__global__ void __launch_bounds__(512) oproj_kernel(const float* __restrict__ bo, float* __restrict__ out) {
    __shared__ float esc[8][HH][NSPLIT];
    __shared__ __align__(16) ull in_dup[8][DD];
    int row0 = blockIdx.x * 8;
    int b = row0 >> 9;
    int q0 = row0 & 511;
    int tid = threadIdx.x;
    int cp = tid & 127, rg = tid >> 7;
    if (tid < 64) {
        int r = tid >> 3, h = tid & 7;
        int q = q0 + r;
        float ms[NSPLIT];
        float mx = -1e30f;
        #pragma unroll
        for (int s = 0; s < NSPLIT; s++) {
            ms[s] = g_pm[((b*NSPLIT + s)*HH + h)*NN + q];
            mx = fmaxf(mx, ms[s]);
        }
        float lsum = 0.f;
        #pragma unroll
        for (int s = 0; s < NSPLIT; s++)
            lsum += g_pl[((b*NSPLIT + s)*HH + h)*NN + q] * ex2_fast(ms[s] - mx);
        float inv = 1.0f / lsum;
        #pragma unroll
        for (int s = 0; s < NSPLIT; s++)
            esc[r][h][s] = ex2_fast(ms[s] - mx) * inv;
    }
    __syncthreads();
    int ch0 = 2*cp;
    int h = ch0 >> 5, dh = ch0 & 31;
    #pragma unroll
    for (int rr = 0; rr < 2; rr++) {
        int r = 2*rg + rr;
        float o0 = 0.f, o1 = 0.f;
        #pragma unroll
        for (int s = 0; s < NSPLIT; s++) {
            const float2* base = (const float2*)(g_po + (((b*NSPLIT + s)*HH + h)*NN + q0 + r)*DH + dh);
            float2 pv = base[0];
            float e = esc[r][h][s];
            o0 = fmaf(pv.x, e, o0);
            o1 = fmaf(pv.y, e, o1);
        }
        in_dup[r][ch0]   = pk2(o0, o0);
        in_dup[r][ch0+1] = pk2(o1, o1);
    }
    __syncthreads();
    ull acc0, acc1;
    { float2 bb = ((const float2*)bo)[cp]; acc0 = pk2(bb.x, bb.y); acc1 = acc0; }
    gemm_pair<KQD, 128>(g_Wov + cp,
                        (const ulonglong2*)in_dup[2*rg],
                        (const ulonglong2*)in_dup[2*rg+1], acc0, acc1);
    {
        float2 a = up2(acc0), bq = up2(acc1);
        float2* o0p = (float2*)(out + (row0 + 2*rg)*DD) + cp;
        float2* o1p = (float2*)(out + (row0 + 2*rg+1)*DD) + cp;
        float2 v0 = *o0p, v1 = *o1p;
        v0.x += a.x;  v0.y += a.y;
        v1.x += bq.x; v1.y += bq.y;
        *o0p = v0; *o1p = v1;
    }
}

// ---------------- launch ----------------
extern "C" void kernel_launch(void* const* d_in, const int* in_sizes, int n_in,
                              void* d_out, int out_size) {
    const float* x    = (const float*)d_in[0];
    const float* pf   = (const float*)d_in[1];
    const float* xyz  = (const float*)d_in[2];
    const float* W1   = (const float*)d_in[3];
    const float* b1   = (const float*)d_in[4];
    const float* g1   = (const float*)d_in[5];
    const float* be1  = (const float*)d_in[6];
    const float* Wr1  = (const float*)d_in[7];
    const float* br1  = (const float*)d_in[8];
    const float* gr1  = (const float*)d_in[9];
    const float* ber1 = (const float*)d_in[10];
    const float* Wr2  = (const float*)d_in[11];
    const float* br2  = (const float*)d_in[12];
    const float* gr2  = (const float*)d_in[13];
    const float* ber2 = (const float*)d_in[14];
    const float* Wg   = (const float*)d_in[15];
    const float* bg   = (const float*)d_in[16];
    const float* gg   = (const float*)d_in[17];
    const float* beg  = (const float*)d_in[18];
    const float* Win  = (const float*)d_in[19];
    const float* bin_ = (const float*)d_in[20];
    const float* Wo   = (const float*)d_in[21];
    const float* bo   = (const float*)d_in[22];
    const float* Ws   = (const float*)d_in[23];
    const float* bs   = (const float*)d_in[24];
    const float* gs   = (const float*)d_in[25];
    const float* bes  = (const float*)d_in[26];
    float* out = (float*)d_out;

    prep_gram_kernel<<<NPREP + 1, 256>>>(W1, Wr1, Wr2, Win, Wo, Wg, Ws, bs);
    local_encoder_kernel<<<128, 512>>>(x, pf, xyz, b1, g1, be1);
    knn_spatial_kernel<<<BB*NN + BB, 256>>>(xyz, Ws, bs, gs, bes, bg, gg, beg, out);
    region_qkv_kernel<<<128, 512>>>(br1, gr1, ber1, br2, gr2, ber2, bin_);
    dim3 ag(NN/64, HH, BB*NSPLIT);
    attn_kernel<<<ag, 64>>>();
    oproj_kernel<<<128, 512>>>(bo, out);
}

// round 13
// speedup vs baseline: 2.4037x; 1.1226x over previous
#include <cuda_runtime.h>
#include <math.h>

#define BB 2
#define NN 512
#define CD 64
#define PF 128
#define DD 256
#define KNN 16
#define HH 8
#define DH 32
#define QKVD 768
#define CIN 195
#define KQ1 49      // ceil(195/4)
#define KQD 64      // 256/4
#define NSPLIT 4

typedef unsigned long long ull;

// ---------------- scratch (device globals) ----------------
__device__ float4 g_W1p[KQ1*DD];
__device__ float4 g_Wr1p[KQD*DD];
__device__ float4 g_Wr2p[KQD*DD];
__device__ float4 g_Winp[KQD*QKVD];
__device__ float4 g_Wop[KQD*DD];
__device__ float4 g_Wgp[KQD*DD];
__device__ float g_mu[5];
__device__ float g_G[25];
__device__ __align__(16) float g_local[BB*NN*DD];
__device__ __align__(16) float g_regin[BB*NN*DD];
__device__ __align__(16) float g_qkv[BB*NN*QKVD];
__device__ float g_part[128*DD];
__device__ float g_gfeat[BB*DD];
__device__ float g_pm[BB*NSPLIT*HH*NN];
__device__ float g_pl[BB*NSPLIT*HH*NN];
__device__ __align__(16) float g_po[BB*NSPLIT*HH*NN*DH];

// ---------------- f32x2 packed math ----------------
__device__ __forceinline__ ull f2fma(ull a, ull b, ull c){ ull d; asm("fma.rn.f32x2 %0, %1, %2, %3;" : "=l"(d) : "l"(a), "l"(b), "l"(c)); return d; }
__device__ __forceinline__ ull f2mul(ull a, ull b){ ull d; asm("mul.rn.f32x2 %0, %1, %2;" : "=l"(d) : "l"(a), "l"(b)); return d; }
__device__ __forceinline__ ull pk2(float lo, float hi){ ull r; asm("mov.b64 %0, {%1,%2};" : "=l"(r) : "f"(lo), "f"(hi)); return r; }
__device__ __forceinline__ float2 up2(ull v){ float2 r; asm("mov.b64 {%0,%1}, %2;" : "=f"(r.x), "=f"(r.y) : "l"(v)); return r; }
__device__ __forceinline__ float rcp_fast(float x){ float r; asm("rcp.approx.ftz.f32 %0, %1;" : "=f"(r) : "f"(x)); return r; }
__device__ __forceinline__ float ex2_fast(float x){ float r; asm("ex2.approx.ftz.f32 %0, %1;" : "=f"(r) : "f"(x)); return r; }

__device__ __forceinline__ float gelu_fast(float x) {
    float xs = x * 0.70710678118654752440f;
    float ax = fabsf(xs);
    float t  = rcp_fast(fmaf(0.3275911f, ax, 1.0f));
    float p  = t * fmaf(t, fmaf(t, fmaf(t, fmaf(t, 1.061405429f, -1.453152027f),
                       1.421413741f), -0.284496736f), 0.254829592f);
    float e  = ex2_fast(-xs * xs * 1.4426950408889634f);
    float erfv = fmaf(-p, e, 1.0f);
    erfv = copysignf(erfv, xs);
    return 0.5f * x * (1.0f + erfv);
}

// ---------------- K0: weight packing + 5x5 Gram (R6 formulation) ----------------
__device__ __forceinline__ float blockSumAll(float v, float* red) {
    #pragma unroll
    for (int o = 16; o > 0; o >>= 1) v += __shfl_down_sync(0xffffffffu, v, o);
    int w = threadIdx.x >> 5, l = threadIdx.x & 31;
    __syncthreads();
    if (l == 0) red[w] = v;
    __syncthreads();
    return red[0]+red[1]+red[2]+red[3]+red[4]+red[5]+red[6]+red[7];
}

#define NPREP 64
__global__ void prep_gram_kernel(const float* __restrict__ W1, const float* __restrict__ Wr1,
                                 const float* __restrict__ Wr2, const float* __restrict__ Win,
                                 const float* __restrict__ Wo, const float* __restrict__ Wg,
                                 const float* __restrict__ Ws, const float* __restrict__ bs) {
    if (blockIdx.x < NPREP) {
        int i = blockIdx.x * 256 + threadIdx.x;
        int stride = NPREP * 256;
        for (int e = i; e < DD*KQ1; e += stride) {
            int d = e / KQ1, kq = e % KQ1;
            int k = kq * 4;
            float4 v;
            v.x = (k+0 < CIN) ? W1[d*CIN + k+0] : 0.f;
            v.y = (k+1 < CIN) ? W1[d*CIN + k+1] : 0.f;
            v.z = (k+2 < CIN) ? W1[d*CIN + k+2] : 0.f;
            v.w = (k+3 < CIN) ? W1[d*CIN + k+3] : 0.f;
            g_W1p[kq*DD + d] = v;
        }
        for (int e = i; e < DD*KQD; e += stride) {
            int d = e >> 6, kq = e & 63;
            g_Wr1p[kq*DD + d] = ((const float4*)(Wr1 + d*DD))[kq];
            g_Wr2p[kq*DD + d] = ((const float4*)(Wr2 + d*DD))[kq];
            g_Wop [kq*DD + d] = ((const float4*)(Wo  + d*DD))[kq];
            g_Wgp [kq*DD + d] = ((const float4*)(Wg  + d*DD))[kq];
        }
        for (int e = i; e < QKVD*KQD; e += stride) {
            int ch = e >> 6, kq = e & 63;
            g_Winp[kq*QKVD + ch] = ((const float4*)(Win + ch*DD))[kq];
        }
    } else {
        __shared__ float red[8];
        int d = threadIdx.x;
        float4 w4 = *(const float4*)(Ws + d*4);
        float v[5] = {w4.x, w4.y, w4.z, w4.w, bs[d]};
        float mu[5];
        #pragma unroll
        for (int p = 0; p < 5; p++) mu[p] = blockSumAll(v[p], red) * (1.0f/DD);
        #pragma unroll
        for (int p = 0; p < 5; p++) v[p] -= mu[p];
        for (int p = 0; p < 5; p++)
            for (int q = 0; q < 5; q++) {
                float s = blockSumAll(v[p]*v[q], red) * (1.0f/DD);
                if (d == 0) g_G[p*5 + q] = s;
            }
        if (d == 0) { for (int p = 0; p < 5; p++) g_mu[p] = mu[p]; }
    }
}

// ---------------- LN stats helpers (512-thread blocks) ----------------
__device__ __forceinline__ void ln_rows8_512(float (*h_sh)[DD], float (*stat)[2]) {
    int w = threadIdx.x >> 5, l = threadIdx.x & 31;
    if (w < 8) {
        float s = 0.f, s2 = 0.f;
        #pragma unroll
        for (int i = l; i < DD; i += 32) { float v = h_sh[w][i]; s += v; s2 += v*v; }
        #pragma unroll
        for (int o = 16; o > 0; o >>= 1) {
            s  += __shfl_down_sync(0xffffffffu, s,  o);
            s2 += __shfl_down_sync(0xffffffffu, s2, o);
        }
        if (l == 0) {
            float m = s * (1.0f/DD);
            stat[w][0] = m;
            stat[w][1] = rsqrtf(s2 * (1.0f/DD) - m*m + 1e-5f);
        }
    }
    __syncthreads();
}

__device__ __forceinline__ void ln_rows4_512(float (*h_sh)[DD], float (*stat)[2]) {
    int w = threadIdx.x >> 5, l = threadIdx.x & 31;
    if (w < 4) {
        float s = 0.f, s2 = 0.f;
        #pragma unroll
        for (int i = l; i < DD; i += 32) { float v = h_sh[w][i]; s += v; s2 += v*v; }
        #pragma unroll
        for (int o = 16; o > 0; o >>= 1) {
            s  += __shfl_down_sync(0xffffffffu, s,  o);
            s2 += __shfl_down_sync(0xffffffffu, s2, o);
        }
        if (l == 0) {
            float m = s * (1.0f/DD);
            stat[w][0] = m;
            stat[w][1] = rsqrtf(s2 * (1.0f/DD) - m*m + 1e-5f);
        }
    }
    __syncthreads();
}

// ---------------- K1: local encoder (R6 formulation, 8 rows/block) ----------------
__global__ void __launch_bounds__(512) local_encoder_kernel(
        const float* __restrict__ x, const float* __restrict__ pf,
        const float* __restrict__ xyz, const float* __restrict__ b1,
        const float* __restrict__ g1, const float* __restrict__ be1) {
    __shared__ __align__(16) ull in_pk[4][196];   // (row2p, row2p+1) packed
    __shared__ float h_sh[8][DD];
    __shared__ float stat[8][2];
    __shared__ float part_sh[2][DD];
    int row0 = blockIdx.x * 8;
    int tid = threadIdx.x;
    int ch = tid & 255, rg = tid >> 8;   // pairs 2rg, 2rg+1; rows 4rg..4rg+3
    for (int idx = tid; idx < 4*196; idx += 512) {
        int p = idx / 196, k = idx % 196;
        int r0 = row0 + 2*p;
        float v0, v1;
        if (k < CD)           { v0 = x[r0*CD + k];               v1 = x[(r0+1)*CD + k]; }
        else if (k < CD+PF)   { v0 = pf[r0*PF + (k-CD)];         v1 = pf[(r0+1)*PF + (k-CD)]; }
        else if (k < CIN)     { v0 = xyz[r0*3 + (k-CD-PF)];      v1 = xyz[(r0+1)*3 + (k-CD-PF)]; }
        else                  { v0 = 0.f; v1 = 0.f; }
        in_pk[p][k] = pk2(v0, v1);
    }
    __syncthreads();
    ull acc0, acc1;
    {
        float bb = b1[ch];
        acc0 = pk2(bb, bb); acc1 = acc0;
    }
    #pragma unroll 4
    for (int kq = 0; kq < KQ1; kq++) {
        float4 w = g_W1p[kq*DD + ch];
        ull wx = pk2(w.x,w.x), wy = pk2(w.y,w.y), wz = pk2(w.z,w.z), ww = pk2(w.w,w.w);
        const ulonglong2* pa = (const ulonglong2*)&in_pk[2*rg][kq*4];
        const ulonglong2* pb = (const ulonglong2*)&in_pk[2*rg+1][kq*4];
        ulonglong2 a01 = pa[0], a23 = pa[1];
        ulonglong2 b01 = pb[0], b23 = pb[1];
        acc0 = f2fma(wx, a01.x, acc0); acc0 = f2fma(wy, a01.y, acc0);
        acc0 = f2fma(wz, a23.x, acc0); acc0 = f2fma(ww, a23.y, acc0);
        acc1 = f2fma(wx, b01.x, acc1); acc1 = f2fma(wy, b01.y, acc1);
        acc1 = f2fma(wz, b23.x, acc1); acc1 = f2fma(ww, b23.y, acc1);
    }
    {
        float2 a = up2(acc0), b = up2(acc1);
        h_sh[4*rg+0][ch] = a.x; h_sh[4*rg+1][ch] = a.y;
        h_sh[4*rg+2][ch] = b.x; h_sh[4*rg+3][ch] = b.y;
    }
    __syncthreads();
    ln_rows8_512(h_sh, stat);
    float gv = g1[ch], bev = be1[ch];
    float psum = 0.f;
    #pragma unroll
    for (int r = 0; r < 4; r++) {
        int row = rg*4 + r;
        float t = (h_sh[row][ch] - stat[row][0]) * stat[row][1] * gv + bev;
        float g = gelu_fast(t);
        psum += g;
        g_local[(row0 + row)*DD + ch] = g;
    }
    part_sh[rg][ch] = psum;
    __syncthreads();
    if (tid < 256)
        g_part[blockIdx.x*DD + tid] = part_sh[0][tid] + part_sh[1][tid];
}

// ---------------- K2: fused gfeat(2 blocks) + kNN + gather + spatial ----------------
__global__ void knn_spatial_kernel(const float* __restrict__ xyz, const float* __restrict__ Ws,
                                   const float* __restrict__ bs, const float* __restrict__ gs,
                                   const float* __restrict__ bes,
                                   const float* __restrict__ bg, const float* __restrict__ gg,
                                   const float* __restrict__ beg,
                                   float* __restrict__ out) {
    __shared__ __align__(16) float xs[NN*3];
    __shared__ float  d2s[NN];
    __shared__ __align__(16) float sPXY[NN*2];
    __shared__ __align__(16) float sPZR[NN*2];
    __shared__ __align__(16) float sIM[NN*2];
    __shared__ float  wV[8*KNN];
    __shared__ int    wI[8*KNN];
    __shared__ int    sel[KNN];
    __shared__ float  sums6[6];
    __shared__ float  red6[8][6];
    int tid = threadIdx.x;
    int lane = tid & 31, warp = tid >> 5;

    if (blockIdx.x < BB) {
        float* lm = xs;
        float* red = d2s;
        int b = blockIdx.x;
        float s = 0.f;
        #pragma unroll 16
        for (int blk = 0; blk < 64; blk++) s += g_part[(b*64 + blk)*DD + tid];
        lm[tid] = s * (1.0f/NN);
        __syncthreads();
        float acc = bg[tid];
        for (int kq = 0; kq < KQD; kq++) {
            float4 l4 = ((const float4*)lm)[kq];
            float4 w = g_Wgp[kq*DD + tid];
            acc = fmaf(l4.x, w.x, acc);
            acc = fmaf(l4.y, w.y, acc);
            acc = fmaf(l4.z, w.z, acc);
            acc = fmaf(l4.w, w.w, acc);
        }
        float sv = acc, s2 = acc*acc;
        #pragma unroll
        for (int o = 16; o > 0; o >>= 1) {
            sv += __shfl_down_sync(0xffffffffu, sv, o);
            s2 += __shfl_down_sync(0xffffffffu, s2, o);
        }
        if (lane == 0) { red[warp] = sv; red[8 + warp] = s2; }
        __syncthreads();
        float S = 0.f, S2 = 0.f;
        #pragma unroll
        for (int t = 0; t < 8; t++) { S += red[t]; S2 += red[8 + t]; }
        float m = S * (1.0f/DD);
        float is = rsqrtf(S2 * (1.0f/DD) - m*m + 1e-5f);
        g_gfeat[b*DD + tid] = (acc - m) * is * gg[tid] + beg[tid];
        return;
    }

    int bid = blockIdx.x - BB;
    int b = bid >> 9, i = bid & 511;
    for (int idx = tid; idx < NN*3; idx += 256) xs[idx] = xyz[b*NN*3 + idx];
    __syncthreads();
    float xi = xs[i*3], yi = xs[i*3+1], zi = xs[i*3+2];
    float lsx = 0.f, lsy = 0.f, lsz = 0.f, lsr = 0.f, lsi = 0.f, lsm = 0.f;
    #pragma unroll
    for (int jj = 0; jj < 2; jj++) {
        int j = tid + jj*256;
        float a = xi - xs[j*3], bc = yi - xs[j*3+1], c = zi - xs[j*3+2];
        float d2 = a*a + bc*bc + c*c;
        float rd = sqrtf(d2);
        d2s[j] = d2;
        float cf[5] = {a, bc, c, rd, 1.0f};
        float mm = fmaf(a, g_mu[0], fmaf(bc, g_mu[1], fmaf(c, g_mu[2], fmaf(rd, g_mu[3], g_mu[4]))));
        float var = 0.f;
        #pragma unroll
        for (int p = 0; p < 5; p++) {
            float t = 0.f;
            #pragma unroll
            for (int q = 0; q < 5; q++) t = fmaf(g_G[p*5 + q], cf[q], t);
            var = fmaf(cf[p], t, var);
        }
        float is = rsqrtf(var + 1e-5f);
        float px = is*a, py = is*bc, pz = is*c, pr = is*rd, pm = mm*is;
        int base = (j >> 1)*4 + (j & 1);
        sPXY[base]     = px;  sPXY[base + 2] = py;
        sPZR[base]     = pz;  sPZR[base + 2] = pr;
        sIM[base]      = is;  sIM[base + 2]  = pm;
        lsx += px; lsy += py; lsz += pz; lsr += pr; lsi += is; lsm += pm;
    }
    #pragma unroll
    for (int o = 16; o > 0; o >>= 1) {
        lsx += __shfl_down_sync(0xffffffffu, lsx, o);
        lsy += __shfl_down_sync(0xffffffffu, lsy, o);
        lsz += __shfl_down_sync(0xffffffffu, lsz, o);
        lsr += __shfl_down_sync(0xffffffffu, lsr, o);
        lsi += __shfl_down_sync(0xffffffffu, lsi, o);
        lsm += __shfl_down_sync(0xffffffffu, lsm, o);
    }
    if (lane == 0) {
        red6[warp][0] = lsx; red6[warp][1] = lsy; red6[warp][2] = lsz;
        red6[warp][3] = lsr; red6[warp][4] = lsi; red6[warp][5] = lsm;
    }
    __syncthreads();
    if (tid < 6) {
        float t = 0.f;
        #pragma unroll
        for (int w = 0; w < 8; w++) t += red6[w][tid];
        sums6[tid] = t;
    }
    {
        int j0 = warp*64 + lane, j1 = j0 + 32;
        float v0 = d2s[j0], v1 = d2s[j1];
        #pragma unroll
        for (int it = 0; it < KNN; it++) {
            float cv; int ci;
            if (v1 < v0) { cv = v1; ci = j1; } else { cv = v0; ci = j0; }
            #pragma unroll
            for (int o = 16; o > 0; o >>= 1) {
                float ov = __shfl_xor_sync(0xffffffffu, cv, o);
                int   oi = __shfl_xor_sync(0xffffffffu, ci, o);
                if (ov < cv || (ov == cv && oi < ci)) { cv = ov; ci = oi; }
            }
            if (lane == 0) { wV[warp*KNN + it] = cv; wI[warp*KNN + it] = ci; }
            if (ci == j0) v0 = 3.4e38f;
            if (ci == j1) v1 = 3.4e38f;
        }
    }
    __syncthreads();
    if (warp == 0) {
        float mv[4]; int mi[4];
        #pragma unroll
        for (int q = 0; q < 4; q++) { mv[q] = wV[q*32 + lane]; mi[q] = wI[q*32 + lane]; }
        #pragma unroll
        for (int it = 0; it < KNN; it++) {
            float cv = mv[0]; int ci = mi[0];
            #pragma unroll
            for (int q = 1; q < 4; q++)
                if (mv[q] < cv || (mv[q] == cv && mi[q] < ci)) { cv = mv[q]; ci = mi[q]; }
            #pragma unroll
            for (int o = 16; o > 0; o >>= 1) {
                float ov = __shfl_xor_sync(0xffffffffu, cv, o);
                int   oi = __shfl_xor_sync(0xffffffffu, ci, o);
                if (ov < cv || (ov == cv && oi < ci)) { cv = ov; ci = oi; }
            }
            if (lane == 0) sel[it] = ci;
            #pragma unroll
            for (int q = 0; q < 4; q++) if (mi[q] == ci) mv[q] = 3.4e38f;
        }
    }
    __syncthreads();
    float sg = 0.f;
    #pragma unroll
    for (int k = 0; k < KNN; k++) sg += g_local[(b*NN + sel[k])*DD + tid];
    g_regin[(b*NN + i)*DD + tid] = sg * (1.0f/KNN);
    float4 wv4 = *(const float4*)(Ws + tid*4);
    float gd = gs[tid], bed = bes[tid];
    float wxp = gd*wv4.x, wyp = gd*wv4.y, wzp = gd*wv4.z, wwp = gd*wv4.w;
    float bsp = gd*bs[tid];
    float sumT = wxp*sums6[0] + wyp*sums6[1] + wzp*sums6[2] + wwp*sums6[3]
               + bsp*sums6[4] - gd*sums6[5] + bed*(float)NN;
    const ull WX = pk2(wxp, wxp), WY = pk2(wyp, wyp);
    const ull WZ = pk2(wzp, wzp), WW = pk2(wwp, wwp);
    const ull BSP = pk2(bsp, bsp), NGD = pk2(-gd, -gd), BED = pk2(bed, bed);
    const ull ONE2  = pk2(1.0f, 1.0f);
    const ull ISQ2  = pk2(0.70710678118654752440f, 0.70710678118654752440f);
    const ull CP    = pk2(0.47047f, 0.47047f);
    const ull C3    = pk2(-0.7478556f, -0.7478556f);
    const ull C2    = pk2(0.0958798f, 0.0958798f);
    const ull C1    = pk2(-0.3480242f, -0.3480242f);
    const ull NL2E  = pk2(-1.4426950408889634f, -1.4426950408889634f);
    const ull ABSM  = 0x7FFFFFFF7FFFFFFFull;
    const ull SGNM  = 0x8000000080000000ull;
    const ulonglong2* pXY = (const ulonglong2*)sPXY;
    const ulonglong2* pZR = (const ulonglong2*)sPZR;
    const ulonglong2* pIM = (const ulonglong2*)sIM;
    ull acc2 = 0ull;
    #pragma unroll 2
    for (int j2 = 0; j2 < NN/2; j2++) {
        ulonglong2 axy = pXY[j2];
        ulonglong2 azr = pZR[j2];
        ulonglong2 aim = pIM[j2];
        ull t = f2fma(NGD, aim.y, BED);
        t = f2fma(BSP, aim.x, t);
        t = f2fma(WW, azr.y, t);
        t = f2fma(WZ, azr.x, t);
        t = f2fma(WY, axy.y, t);
        t = f2fma(WX, axy.x, t);
        ull xsp = f2mul(t, ISQ2);
        ull axp = xsp & ABSM;
        ull den = f2fma(axp, CP, ONE2);
        float2 dv = up2(den);
        ull tt = pk2(rcp_fast(dv.x), rcp_fast(dv.y));
        ull p = f2fma(C3, tt, C2);
        p = f2fma(p, tt, C1);
        p = f2mul(p, tt);
        ull m2 = f2mul(xsp, xsp);
        ull ea = f2mul(m2, NL2E);
        float2 ev = up2(ea);
        ull e2 = pk2(ex2_fast(ev.x), ex2_fast(ev.y));
        ull erf2 = f2fma(p, e2, ONE2);
        erf2 = erf2 | (xsp & SGNM);
        acc2 = f2fma(t, erf2, acc2);
    }
    float2 av = up2(acc2);
    out[(b*NN + i)*DD + tid] = 0.5f * (sumT + av.x + av.y) * (1.0f/NN);
}

// ---------------- K3: region MLP + combined + QKV (4 rows/block, 256 blocks) ----------------
__global__ void __launch_bounds__(512) region_qkv_kernel(
        const float* __restrict__ br1, const float* __restrict__ gr1,
        const float* __restrict__ ber1, const float* __restrict__ br2,
        const float* __restrict__ gr2, const float* __restrict__ ber2,
        const float* __restrict__ bin_) {
    __shared__ __align__(16) ull in_pk[2][DD];     // pair p = rows (row0+2p, row0+2p+1)
    __shared__ float h_sh[4][DD];
    __shared__ float stat[4][2];
    int row0 = blockIdx.x * 4;
    int b = row0 >> 9;
    int tid = threadIdx.x;
    int ch = tid & 255, rg = tid >> 8;             // rg = this thread's pair
    // load regin pair-packed (each thread loads exactly its (rg,ch))
    in_pk[rg][ch] = pk2(g_regin[(row0 + 2*rg)*DD + ch], g_regin[(row0 + 2*rg + 1)*DD + ch]);
    __syncthreads();
    const ulonglong2* pa = (const ulonglong2*)in_pk[rg];
    ull acc0;
    { float bb = br1[ch]; acc0 = pk2(bb, bb); }
    #pragma unroll 4
    for (int kq = 0; kq < KQD; kq++) {
        float4 w = g_Wr1p[kq*DD + ch];
        ull wx = pk2(w.x,w.x), wy = pk2(w.y,w.y), wz = pk2(w.z,w.z), ww = pk2(w.w,w.w);
        ulonglong2 a01 = pa[2*kq], a23 = pa[2*kq+1];
        acc0 = f2fma(wx, a01.x, acc0); acc0 = f2fma(wy, a01.y, acc0);
        acc0 = f2fma(wz, a23.x, acc0); acc0 = f2fma(ww, a23.y, acc0);
    }
    {
        float2 a = up2(acc0);
        h_sh[2*rg][ch] = a.x; h_sh[2*rg+1][ch] = a.y;
    }
    __syncthreads();
    ln_rows4_512(h_sh, stat);
    {
        float g1 = gr1[ch], b1v = ber1[ch];
        float t0 = (h_sh[2*rg][ch]   - stat[2*rg][0])   * stat[2*rg][1]   * g1 + b1v;
        float t1 = (h_sh[2*rg+1][ch] - stat[2*rg+1][0]) * stat[2*rg+1][1] * g1 + b1v;
        in_pk[rg][ch] = pk2(gelu_fast(t0), gelu_fast(t1));
    }
    __syncthreads();
    { float bb = br2[ch]; acc0 = pk2(bb, bb); }
    #pragma unroll 4
    for (int kq = 0; kq < KQD; kq++) {
        float4 w = g_Wr2p[kq*DD + ch];
        ull wx = pk2(w.x,w.x), wy = pk2(w.y,w.y), wz = pk2(w.z,w.z), ww = pk2(w.w,w.w);
        ulonglong2 a01 = pa[2*kq], a23 = pa[2*kq+1];
        acc0 = f2fma(wx, a01.x, acc0); acc0 = f2fma(wy, a01.y, acc0);
        acc0 = f2fma(wz, a23.x, acc0); acc0 = f2fma(ww, a23.y, acc0);
    }
    __syncthreads();   // all in_pk reads of GEMM2 done before combined overwrite
    {
        float2 a = up2(acc0);
        h_sh[2*rg][ch] = a.x; h_sh[2*rg+1][ch] = a.y;
    }
    __syncthreads();
    ln_rows4_512(h_sh, stat);
    {
        float g2 = gr2[ch], b2v = ber2[ch];
        float gf = g_gfeat[b*DD + ch];
        float t0 = (h_sh[2*rg][ch]   - stat[2*rg][0])   * stat[2*rg][1]   * g2 + b2v;
        float t1 = (h_sh[2*rg+1][ch] - stat[2*rg+1][0]) * stat[2*rg+1][1] * g2 + b2v;
        float c0 = g_local[(row0 + 2*rg)*DD + ch] + t0 + gf;
        float c1 = g_local[(row0 + 2*rg + 1)*DD + ch] + t1 + gf;
        in_pk[rg][ch] = pk2(c0, c1);
    }
    __syncthreads();
    // ---- QKV GEMM: 3 output groups fused in one kq loop for ILP ----
    ull qa[3];
    #pragma unroll
    for (int co = 0; co < 3; co++) {
        float bb = bin_[co*256 + ch];
        qa[co] = pk2(bb, bb);
    }
    #pragma unroll 2
    for (int kq = 0; kq < KQD; kq++) {
        ulonglong2 a01 = pa[2*kq], a23 = pa[2*kq+1];
        #pragma unroll
        for (int co = 0; co < 3; co++) {
            float4 w = g_Winp[kq*QKVD + co*256 + ch];
            ull wx = pk2(w.x,w.x), wy = pk2(w.y,w.y), wz = pk2(w.z,w.z), ww = pk2(w.w,w.w);
            qa[co] = f2fma(wx, a01.x, qa[co]); qa[co] = f2fma(wy, a01.y, qa[co]);
            qa[co] = f2fma(wz, a23.x, qa[co]); qa[co] = f2fma(ww, a23.y, qa[co]);
        }
    }
    #pragma unroll
    for (int co = 0; co < 3; co++) {
        float2 a = up2(qa[co]);
        g_qkv[(row0 + 2*rg)*QKVD + co*256 + ch]     = a.x;
        g_qkv[(row0 + 2*rg + 1)*QKVD + co*256 + ch] = a.y;
    }
}

// ---------------- K4: attention split-KV, f32x2-packed ----------------
__global__ void attn_kernel() {
    __shared__ __align__(16) float Ksh[128][DH];
    __shared__ __align__(16) float Vsh[128][DH];
    int z = blockIdx.z;
    int b = z >> 2, s = z & 3;
    int h = blockIdx.y;
    int qi = blockIdx.x * 64 + threadIdx.x;
    int tid = threadIdx.x;
    const float scale = 0.17677669529663688f * 1.4426950408889634f;
    ull qp[16];
    const float* qrow = g_qkv + (b*NN + qi)*QKVD + h*DH;
    #pragma unroll
    for (int d4 = 0; d4 < 8; d4++) {
        float4 v = *(const float4*)(qrow + d4*4);
        qp[d4*2]   = pk2(v.x*scale, v.y*scale);
        qp[d4*2+1] = pk2(v.z*scale, v.w*scale);
    }
    int jt = s * 128;
    for (int idx = tid; idx < 128*DH; idx += 64) {
        int jj = idx >> 5, dd = idx & 31;
        int base = (b*NN + jt + jj)*QKVD + h*DH + dd;
        Ksh[jj][dd] = g_qkv[base + DD];
        Vsh[jj][dd] = g_qkv[base + 2*DD];
    }
    __syncthreads();
    float m = -1e30f, l = 0.f;
    ull op[16];
    #pragma unroll
    for (int t = 0; t < 16; t++) op[t] = 0ull;
    for (int jj = 0; jj < 128; jj++) {
        const ulonglong2* kp = (const ulonglong2*)Ksh[jj];
        ull s2a = 0ull, s2b = 0ull;
        #pragma unroll
        for (int t = 0; t < 8; t++) {
            ulonglong2 kv = kp[t];
            s2a = f2fma(qp[t*2],   kv.x, s2a);
            s2b = f2fma(qp[t*2+1], kv.y, s2b);
        }
        float2 sva = up2(s2a), svb = up2(s2b);
        float sc = (sva.x + sva.y) + (svb.x + svb.y);
        if (sc > m) {
            float corr = ex2_fast(m - sc);
            l *= corr;
            ull c2 = pk2(corr, corr);
            #pragma unroll
            for (int t = 0; t < 16; t++) op[t] = f2mul(op[t], c2);
            m = sc;
        }
        float p = ex2_fast(sc - m);
        l += p;
        ull pp = pk2(p, p);
        const ulonglong2* vp = (const ulonglong2*)Vsh[jj];
        #pragma unroll
        for (int t = 0; t < 8; t++) {
            ulonglong2 vv = vp[t];
            op[t*2]   = f2fma(pp, vv.x, op[t*2]);
            op[t*2+1] = f2fma(pp, vv.y, op[t*2+1]);
        }
    }
    int pb = ((b*NSPLIT + s)*HH + h)*NN + qi;
    g_pm[pb] = m;
    g_pl[pb] = l;
    float* po = g_po + pb*DH;
    #pragma unroll
    for (int t = 0; t < 16; t++) {
        float2 ov = up2(op[t]);
        po[t*2]   = ov.x;
        po[t*2+1] = ov.y;
    }
}

// ---------------- K5: merge splits + out += o @ Wo.T + bo (R6 formulation) ----------------
__global__ void __launch_bounds__(512) oproj_kernel(const float* __restrict__ bo, float* __restrict__ out) {
    __shared__ float esc[8][HH][NSPLIT];
    __shared__ __align__(16) ull in_pk[4][DD];
    int row0 = blockIdx.x * 8;
    int b = row0 >> 9;
    int q0 = row0 & 511;
    int tid = threadIdx.x;
    int ch = tid & 255, rg = tid >> 8;
    if (tid < 64) {
        int r = tid >> 3, h = tid & 7;
        int q = q0 + r;
        float ms[NSPLIT];
        float mx = -1e30f;
        #pragma unroll
        for (int s = 0; s < NSPLIT; s++) {
            ms[s] = g_pm[((b*NSPLIT + s)*HH + h)*NN + q];
            mx = fmaxf(mx, ms[s]);
        }
        float lsum = 0.f;
        #pragma unroll
        for (int s = 0; s < NSPLIT; s++)
            lsum += g_pl[((b*NSPLIT + s)*HH + h)*NN + q] * ex2_fast(ms[s] - mx);
        float inv = 1.0f / lsum;
        #pragma unroll
        for (int s = 0; s < NSPLIT; s++)
            esc[r][h][s] = ex2_fast(ms[s] - mx) * inv;
    }
    __syncthreads();
    int h = ch >> 5, dh = ch & 31;
    #pragma unroll
    for (int p = 0; p < 2; p++) {
        int r0 = 4*rg + 2*p;
        float o0 = 0.f, o1 = 0.f;
        #pragma unroll
        for (int s = 0; s < NSPLIT; s++) {
            const float* base = g_po + (((b*NSPLIT + s)*HH + h)*NN + q0)*DH + dh;
            o0 = fmaf(base[(r0)*DH],     esc[r0][h][s],   o0);
            o1 = fmaf(base[(r0+1)*DH],   esc[r0+1][h][s], o1);
        }
        in_pk[2*rg + p][ch] = pk2(o0, o1);
    }
    __syncthreads();
    ull acc0, acc1;
    { float bb = bo[ch]; acc0 = pk2(bb, bb); acc1 = acc0; }
    #pragma unroll 4
    for (int kq = 0; kq < KQD; kq++) {
        float4 w = g_Wop[kq*DD + ch];
        ull wx = pk2(w.x,w.x), wy = pk2(w.y,w.y), wz = pk2(w.z,w.z), ww = pk2(w.w,w.w);
        const ulonglong2* pa = (const ulonglong2*)&in_pk[2*rg][kq*4];
        const ulonglong2* pb = (const ulonglong2*)&in_pk[2*rg+1][kq*4];
        ulonglong2 a01 = pa[0], a23 = pa[1];
        ulonglong2 b01 = pb[0], b23 = pb[1];
        acc0 = f2fma(wx, a01.x, acc0); acc0 = f2fma(wy, a01.y, acc0);
        acc0 = f2fma(wz, a23.x, acc0); acc0 = f2fma(ww, a23.y, acc0);
        acc1 = f2fma(wx, b01.x, acc1); acc1 = f2fma(wy, b01.y, acc1);
        acc1 = f2fma(wz, b23.x, acc1); acc1 = f2fma(ww, b23.y, acc1);
    }
    {
        float2 a = up2(acc0), bq = up2(acc1);
        out[(row0 + 4*rg + 0)*DD + ch] += a.x;
        out[(row0 + 4*rg + 1)*DD + ch] += a.y;
        out[(row0 + 4*rg + 2)*DD + ch] += bq.x;
        out[(row0 + 4*rg + 3)*DD + ch] += bq.y;
    }
}

// ---------------- launch ----------------
extern "C" void kernel_launch(void* const* d_in, const int* in_sizes, int n_in,
                              void* d_out, int out_size) {
    const float* x    = (const float*)d_in[0];
    const float* pf   = (const float*)d_in[1];
    const float* xyz  = (const float*)d_in[2];
    const float* W1   = (const float*)d_in[3];
    const float* b1   = (const float*)d_in[4];
    const float* g1   = (const float*)d_in[5];
    const float* be1  = (const float*)d_in[6];
    const float* Wr1  = (const float*)d_in[7];
    const float* br1  = (const float*)d_in[8];
    const float* gr1  = (const float*)d_in[9];
    const float* ber1 = (const float*)d_in[10];
    const float* Wr2  = (const float*)d_in[11];
    const float* br2  = (const float*)d_in[12];
    const float* gr2  = (const float*)d_in[13];
    const float* ber2 = (const float*)d_in[14];
    const float* Wg   = (const float*)d_in[15];
    const float* bg   = (const float*)d_in[16];
    const float* gg   = (const float*)d_in[17];
    const float* beg  = (const float*)d_in[18];
    const float* Win  = (const float*)d_in[19];
    const float* bin_ = (const float*)d_in[20];
    const float* Wo   = (const float*)d_in[21];
    const float* bo   = (const float*)d_in[22];
    const float* Ws   = (const float*)d_in[23];
    const float* bs   = (const float*)d_in[24];
    const float* gs   = (const float*)d_in[25];
    const float* bes  = (const float*)d_in[26];
    float* out = (float*)d_out;

    prep_gram_kernel<<<NPREP + 1, 256>>>(W1, Wr1, Wr2, Win, Wo, Wg, Ws, bs);
    local_encoder_kernel<<<128, 512>>>(x, pf, xyz, b1, g1, be1);
    knn_spatial_kernel<<<BB*NN + BB, 256>>>(xyz, Ws, bs, gs, bes, bg, gg, beg, out);
    region_qkv_kernel<<<256, 512>>>(br1, gr1, ber1, br2, gr2, ber2, bin_);
    dim3 ag(NN/64, HH, BB*NSPLIT);
    attn_kernel<<<ag, 64>>>();
    oproj_kernel<<<128, 512>>>(bo, out);
}